// round 9
// baseline (speedup 1.0000x reference)
#include <cuda_runtime.h>
#include <cuda_bf16.h>
#include <cstdint>

#define B_    64
#define Himg  56
#define Wimg  56
#define C_    128
#define N_    3136
#define NHEAD 4
#define M_TOT (B_ * N_)     // 200704

// Scratch (allocation-free rule: device globals)
__device__ float g_qkv[(size_t)M_TOT * 384];           // 308 MB
__device__ float g_attn[(size_t)M_TOT * C_];           // 103 MB
__device__ __nv_bfloat16 g_wh[512 * 128];              // weights hi (qkv rows 0..383, proj 384..511)
__device__ __nv_bfloat16 g_wl[512 * 128];              // weights lo

// ============================================================================
// Weight split prep: fp32 -> bf16 hi/lo
// ============================================================================
__global__ void prep_weights(const float* __restrict__ w_qkv,
                             const float* __restrict__ w_proj)
{
    int idx = blockIdx.x * 256 + threadIdx.x;
    if (idx >= 512 * 128) return;
    float w = (idx < 384 * 128) ? w_qkv[idx] : w_proj[idx - 384 * 128];
    __nv_bfloat16 hi = __float2bfloat16(w);
    float r = w - __bfloat162float(hi);
    g_wh[idx] = hi;
    g_wl[idx] = __float2bfloat16(r);
}

// ============================================================================
// HMMA GEMM (R8 config, measured-good): C[M, ldc] = A[M,128] @ W[N,128]^T.
// Tile 128x128, 256 threads (8 warps, 4x2), warp tile 32x64, A-reuse loop.
// ============================================================================
#define LDT 136                      // padded row stride in bf16 elements
#define TILE_B (128 * LDT * 2)       // 34816 B per tile
#define SM_AHI 0
#define SM_ALO (TILE_B)
#define SM_WHI (2 * TILE_B)
#define SM_WLO (3 * TILE_B)
#define SM_BYTES (4 * TILE_B)

__device__ __forceinline__ uint32_t smem_u32(const void* p) {
    uint32_t a;
    asm("{ .reg .u64 t; cvta.to.shared.u64 t, %1; cvt.u32.u64 %0, t; }" : "=r"(a) : "l"(p));
    return a;
}

__device__ __forceinline__ uint32_t pack2(float a, float b) {
    __nv_bfloat16 ha = __float2bfloat16(a), hb = __float2bfloat16(b);
    unsigned short ua = reinterpret_cast<unsigned short&>(ha);
    unsigned short ub = reinterpret_cast<unsigned short&>(hb);
    return (uint32_t)ua | ((uint32_t)ub << 16);
}

__device__ __forceinline__ void mma16816(float* d, const uint32_t* a, const uint32_t* b) {
    asm volatile(
        "mma.sync.aligned.m16n8k16.row.col.f32.bf16.bf16.f32 "
        "{%0,%1,%2,%3}, {%4,%5,%6,%7}, {%8,%9}, {%0,%1,%2,%3};"
        : "+f"(d[0]), "+f"(d[1]), "+f"(d[2]), "+f"(d[3])
        : "r"(a[0]), "r"(a[1]), "r"(a[2]), "r"(a[3]), "r"(b[0]), "r"(b[1]));
}

__global__ void __launch_bounds__(256)
hmma_gemm(const float* __restrict__ A,
          const __nv_bfloat16* __restrict__ whi,
          const __nv_bfloat16* __restrict__ wlo,
          float* __restrict__ C, int ldc, int ntiles,
          const float* __restrict__ bias)
{
    extern __shared__ char smem[];
    const uint32_t sb = smem_u32(smem);
    const int tid = threadIdx.x;
    const int wid = tid >> 5;
    const int lane = tid & 31;
    const int m0 = blockIdx.x * 128;

    // ---- Load + split A tile (128 x 128 fp32 -> bf16 hi/lo), once ----
#pragma unroll
    for (int it = 0; it < 8; it++) {
        int e = it * 256 + tid;
        int r = e >> 4;
        int k0 = (e & 15) * 8;
        const float4* p = reinterpret_cast<const float4*>(A + (size_t)(m0 + r) * 128 + k0);
        float4 x0 = p[0], x1 = p[1];
        float f[8] = {x0.x, x0.y, x0.z, x0.w, x1.x, x1.y, x1.z, x1.w};
        uint32_t h[4], l[4];
#pragma unroll
        for (int j = 0; j < 4; j++) {
            float a = f[2 * j], b = f[2 * j + 1];
            __nv_bfloat16 ha = __float2bfloat16(a), hb = __float2bfloat16(b);
            float ra = a - __bfloat162float(ha);
            float rb = b - __bfloat162float(hb);
            unsigned short ua = reinterpret_cast<unsigned short&>(ha);
            unsigned short ub = reinterpret_cast<unsigned short&>(hb);
            h[j] = (uint32_t)ua | ((uint32_t)ub << 16);
            l[j] = pack2(ra, rb);
        }
        uint32_t off = (uint32_t)(r * LDT + k0) * 2;
        *reinterpret_cast<uint4*>(smem + SM_AHI + off) = make_uint4(h[0], h[1], h[2], h[3]);
        *reinterpret_cast<uint4*>(smem + SM_ALO + off) = make_uint4(l[0], l[1], l[2], l[3]);
    }

    const int mrow = (wid & 3) * 32;
    const int ncol = (wid >> 2) * 64;
    const int grp = lane >> 2;
    const int thr4 = lane & 3;

    for (int nt = 0; nt < ntiles; nt++) {
        const int n0 = nt * 128;
#pragma unroll
        for (int it = 0; it < 8; it++) {
            int e = it * 256 + tid;
            int r = e >> 4;
            int k0 = (e & 15) * 8;
            uint32_t off = (uint32_t)(r * LDT + k0) * 2;
            *reinterpret_cast<uint4*>(smem + SM_WHI + off) =
                *reinterpret_cast<const uint4*>(whi + (size_t)(n0 + r) * 128 + k0);
            *reinterpret_cast<uint4*>(smem + SM_WLO + off) =
                *reinterpret_cast<const uint4*>(wlo + (size_t)(n0 + r) * 128 + k0);
        }
        __syncthreads();

        float acc[2][8][4];
#pragma unroll
        for (int mt = 0; mt < 2; mt++)
#pragma unroll
            for (int ntt = 0; ntt < 8; ntt++)
#pragma unroll
                for (int j = 0; j < 4; j++) acc[mt][ntt][j] = 0.f;

#pragma unroll
        for (int pass = 0; pass < 3; pass++) {
            const uint32_t sA = sb + ((pass == 2) ? SM_ALO : SM_AHI);
            const uint32_t sB = sb + ((pass == 1) ? SM_WLO : SM_WHI);
#pragma unroll
            for (int ks = 0; ks < 8; ks++) {
                const int k0 = ks * 16;
                uint32_t afr[2][4];
#pragma unroll
                for (int mt = 0; mt < 2; mt++) {
                    int r = mrow + mt * 16 + grp;
                    uint32_t base = sA + (uint32_t)(r * LDT + k0 + thr4 * 2) * 2;
                    asm volatile("ld.shared.b32 %0, [%1];" : "=r"(afr[mt][0]) : "r"(base));
                    asm volatile("ld.shared.b32 %0, [%1];" : "=r"(afr[mt][1]) : "r"(base + 8 * LDT * 2));
                    asm volatile("ld.shared.b32 %0, [%1];" : "=r"(afr[mt][2]) : "r"(base + 16));
                    asm volatile("ld.shared.b32 %0, [%1];" : "=r"(afr[mt][3]) : "r"(base + 8 * LDT * 2 + 16));
                }
#pragma unroll
                for (int ntt = 0; ntt < 8; ntt++) {
                    int n = ncol + ntt * 8 + grp;
                    uint32_t base = sB + (uint32_t)(n * LDT + k0 + thr4 * 2) * 2;
                    uint32_t bfr[2];
                    asm volatile("ld.shared.b32 %0, [%1];" : "=r"(bfr[0]) : "r"(base));
                    asm volatile("ld.shared.b32 %0, [%1];" : "=r"(bfr[1]) : "r"(base + 16));
#pragma unroll
                    for (int mt = 0; mt < 2; mt++)
                        mma16816(acc[mt][ntt], afr[mt], bfr);
                }
            }
        }

        // ---- Epilogue ----
#pragma unroll
        for (int mt = 0; mt < 2; mt++) {
            int r0 = m0 + mrow + mt * 16 + grp;
#pragma unroll
            for (int ntt = 0; ntt < 8; ntt++) {
                int c = n0 + ncol + ntt * 8 + thr4 * 2;
                float bx = 0.f, by = 0.f;
                if (bias) { bx = bias[c]; by = bias[c + 1]; }
                float2 v0 = make_float2(acc[mt][ntt][0] + bx, acc[mt][ntt][1] + by);
                float2 v1 = make_float2(acc[mt][ntt][2] + bx, acc[mt][ntt][3] + by);
                *reinterpret_cast<float2*>(C + (size_t)r0 * ldc + c) = v0;
                *reinterpret_cast<float2*>(C + (size_t)(r0 + 8) * ldc + c) = v1;
            }
        }
        __syncthreads();
    }
}

// ============================================================================
// Fused windowed attention + depthwise conv: one block per (b, window, head).
// 224 threads, smem ~35.7 KB. v loaded with 9x9 halo; conv applied at output.
// (This exact arithmetic validated in R6: rel_err 2.355284e-6.)
// ============================================================================
__global__ __launch_bounds__(224) void attn_fused(
    const float* __restrict__ w_lim, const float* __restrict__ b_lim)
{
    const int idx = blockIdx.x;
    const int h = idx & 3;
    const int g = (idx >> 2) & 63;
    const int b = idx >> 8;
    const int gy = g >> 3, gx = g & 7;
    const int Y0 = gy * 7, X0 = gx * 7;

    __shared__ float qs[52][33];
    __shared__ float ks[52][33];
    __shared__ float vs[81][33];
    __shared__ float S[52 * 52];
    __shared__ float wl[32 * 9];
    __shared__ float bl[32];

    const int tid = threadIdx.x;

    // conv weights/bias for this head's 32 channels (288 > 224: strided)
    for (int l = tid; l < 288; l += 224) wl[l] = w_lim[h * 32 * 9 + l];
    if (tid < 32) bl[tid] = b_lim[h * 32 + tid];

    // load q, k (49 x 32)
    for (int l = tid; l < 49 * 32; l += 224) {
        int i = l >> 5, c = l & 31;
        int n = (Y0 + i / 7) * 56 + X0 + (i % 7);
        size_t base = ((size_t)b * N_ + n) * 384 + h * 32 + c;
        qs[i][c] = g_qkv[base];
        ks[i][c] = g_qkv[base + 128];
    }
    if (tid < 96) {
        int r = 49 + tid / 32, c = tid & 31;
        qs[r][c] = 0.f; ks[r][c] = 0.f;
    }
    // load v with 9x9 halo (zero outside image)
    for (int l = tid; l < 81 * 32; l += 224) {
        int j = l >> 5, c = l & 31;
        int Y = Y0 + j / 9 - 1, X = X0 + j % 9 - 1;
        float v = 0.f;
        if ((unsigned)Y < 56u && (unsigned)X < 56u)
            v = g_qkv[((size_t)b * N_ + Y * 56 + X) * 384 + 256 + h * 32 + c];
        vs[j][c] = v;
    }
    __syncthreads();

    const float scale = 0.17677669529663687f;   // 32^-0.5

    // ---- S = scale * q @ k^T : 169 tiles of 4x4 ----
    if (tid < 169) {
        int ti = (tid / 13) * 4, tj = (tid % 13) * 4;
        float acc[4][4];
#pragma unroll
        for (int ii = 0; ii < 4; ii++)
#pragma unroll
            for (int jj = 0; jj < 4; jj++) acc[ii][jj] = 0.f;
#pragma unroll
        for (int c = 0; c < 32; c++) {
            float a[4], bb[4];
#pragma unroll
            for (int ii = 0; ii < 4; ii++) a[ii] = qs[ti + ii][c];
#pragma unroll
            for (int jj = 0; jj < 4; jj++) bb[jj] = ks[tj + jj][c];
#pragma unroll
            for (int ii = 0; ii < 4; ii++)
#pragma unroll
                for (int jj = 0; jj < 4; jj++) acc[ii][jj] += a[ii] * bb[jj];
        }
#pragma unroll
        for (int ii = 0; ii < 4; ii++)
#pragma unroll
            for (int jj = 0; jj < 4; jj++)
                S[(ti + ii) * 52 + tj + jj] = acc[ii][jj] * scale;
    }
    __syncthreads();

    // ---- softmax rows ----
    if (tid < 49) {
        float* row = S + tid * 52;
        float m = -1e30f;
        for (int j = 0; j < 49; j++) m = fmaxf(m, row[j]);
        float s = 0.f;
        for (int j = 0; j < 49; j++) {
            float e = __expf(row[j] - m);
            row[j] = e;
            s += e;
        }
        float inv = __fdividef(1.f, s);
        for (int j = 0; j < 49; j++) row[j] *= inv;
    }
    __syncthreads();

    // ---- O = P @ v (+ conv(v) + bias) : 13 x 8 tiles of 4x4 ----
    if (tid < 104) {
        int ti = (tid >> 3) * 4, td = (tid & 7) * 4;
        float acc[4][4];
#pragma unroll
        for (int ii = 0; ii < 4; ii++)
#pragma unroll
            for (int dd = 0; dd < 4; dd++) acc[ii][dd] = 0.f;
#pragma unroll
        for (int jy = 0; jy < 7; jy++)
#pragma unroll
            for (int jx = 0; jx < 7; jx++) {
                int j = jy * 7 + jx;
                const float* vp = &vs[(jy + 1) * 9 + jx + 1][td];
                float p[4], v[4];
#pragma unroll
                for (int ii = 0; ii < 4; ii++) p[ii] = S[(ti + ii) * 52 + j];
#pragma unroll
                for (int dd = 0; dd < 4; dd++) v[dd] = vp[dd];
#pragma unroll
                for (int ii = 0; ii < 4; ii++)
#pragma unroll
                    for (int dd = 0; dd < 4; dd++) acc[ii][dd] += p[ii] * v[dd];
            }
#pragma unroll
        for (int ii = 0; ii < 4; ii++) {
            int i = ti + ii;
            if (i < 49) {
                int iy = i / 7, ix = i % 7;
                int n = (Y0 + iy) * 56 + X0 + ix;
                size_t ob = ((size_t)b * N_ + n) * 128 + h * 32 + td;
#pragma unroll
                for (int dd = 0; dd < 4; dd++) {
                    int cc = td + dd;
                    float s = bl[cc];
                    const float* w = wl + cc * 9;
#pragma unroll
                    for (int dy = 0; dy < 3; dy++)
#pragma unroll
                        for (int dx = 0; dx < 3; dx++)
                            s += w[dy * 3 + dx] * vs[(iy + dy) * 9 + (ix + dx)][cc];
                    g_attn[ob + dd] = acc[ii][dd] + s;
                }
            }
        }
    }
}

// ============================================================================
extern "C" void kernel_launch(void* const* d_in, const int* in_sizes, int n_in,
                              void* d_out, int out_size)
{
    const float* x      = (const float*)d_in[0];
    const float* w_qkv  = (const float*)d_in[1];
    const float* w_lim  = (const float*)d_in[2];
    const float* b_lim  = (const float*)d_in[3];
    const float* w_proj = (const float*)d_in[4];
    const float* b_proj = (const float*)d_in[5];
    float* out = (float*)d_out;

    float *qkv_ptr, *attn_ptr;
    __nv_bfloat16 *wh_ptr, *wl_ptr;
    cudaGetSymbolAddress((void**)&qkv_ptr,  g_qkv);
    cudaGetSymbolAddress((void**)&attn_ptr, g_attn);
    cudaGetSymbolAddress((void**)&wh_ptr,   g_wh);
    cudaGetSymbolAddress((void**)&wl_ptr,   g_wl);

    cudaFuncSetAttribute(hmma_gemm, cudaFuncAttributeMaxDynamicSharedMemorySize, SM_BYTES);

    // 0) split weights into bf16 hi/lo
    prep_weights<<<(512 * 128 + 255) / 256, 256>>>(w_qkv, w_proj);

    // 1) qkv = x @ w_qkv^T  (A loaded+split once, 3 W tiles)
    hmma_gemm<<<M_TOT / 128, 256, SM_BYTES>>>(x, wh_ptr, wl_ptr, qkv_ptr, 384, 3, nullptr);

    // 2) fused windowed attention + depthwise conv + bias (per head)
    attn_fused<<<B_ * 64 * NHEAD, 224>>>(w_lim, b_lim);

    // 3) out = g_attn @ w_proj^T + b_proj
    hmma_gemm<<<M_TOT / 128, 256, SM_BYTES>>>(attn_ptr, wh_ptr + 384 * 128,
                                              wl_ptr + 384 * 128, out, 128, 1, b_proj);
}

// round 10
// speedup vs baseline: 1.0196x; 1.0196x over previous
#include <cuda_runtime.h>
#include <cuda_bf16.h>
#include <cstdint>

#define B_    64
#define Himg  56
#define Wimg  56
#define C_    128
#define N_    3136
#define NHEAD 4
#define M_TOT (B_ * N_)     // 200704

// Scratch (allocation-free rule: device globals)
__device__ float g_qkv[(size_t)M_TOT * 384];           // 308 MB
__device__ float g_attn[(size_t)M_TOT * C_];           // 103 MB
__device__ __nv_bfloat16 g_wh[512 * 128];              // weights hi (qkv rows 0..383, proj 384..511)
__device__ __nv_bfloat16 g_wl[512 * 128];              // weights lo

// ============================================================================
// Weight split prep: fp32 -> bf16 hi/lo
// ============================================================================
__global__ void prep_weights(const float* __restrict__ w_qkv,
                             const float* __restrict__ w_proj)
{
    int idx = blockIdx.x * 256 + threadIdx.x;
    if (idx >= 512 * 128) return;
    float w = (idx < 384 * 128) ? w_qkv[idx] : w_proj[idx - 384 * 128];
    __nv_bfloat16 hi = __float2bfloat16(w);
    float r = w - __bfloat162float(hi);
    g_wh[idx] = hi;
    g_wl[idx] = __float2bfloat16(r);
}

// ============================================================================
// HMMA GEMM, 3-smem-tile staged (2 CTAs/SM): C = A[M,128] @ W[N,128]^T (+bias)
// Tile 128x128, 256 threads (8 warps, 4x2), warp tile 32x64.
// Slots: T0=Ahi, T1=Alo (later overwritten by Wlo), T2=Whi.
// Passes: hi*hi, lo*hi (Whi), then reload T1<-Wlo, pass hi*lo.
// ============================================================================
#define LDT 136                      // padded row stride in bf16 elements
#define TILE_B (128 * LDT * 2)       // 34816 B per tile
#define SM_AHI 0
#define SM_ALO (TILE_B)              // doubles as Wlo slot later
#define SM_WHI (2 * TILE_B)
#define SM_BYTES (3 * TILE_B)        // 104448 B -> 2 CTAs/SM

__device__ __forceinline__ uint32_t smem_u32(const void* p) {
    uint32_t a;
    asm("{ .reg .u64 t; cvta.to.shared.u64 t, %1; cvt.u32.u64 %0, t; }" : "=r"(a) : "l"(p));
    return a;
}

__device__ __forceinline__ uint32_t pack2(float a, float b) {
    __nv_bfloat16 ha = __float2bfloat16(a), hb = __float2bfloat16(b);
    unsigned short ua = reinterpret_cast<unsigned short&>(ha);
    unsigned short ub = reinterpret_cast<unsigned short&>(hb);
    return (uint32_t)ua | ((uint32_t)ub << 16);
}

__device__ __forceinline__ void mma16816(float* d, const uint32_t* a, const uint32_t* b) {
    asm volatile(
        "mma.sync.aligned.m16n8k16.row.col.f32.bf16.bf16.f32 "
        "{%0,%1,%2,%3}, {%4,%5,%6,%7}, {%8,%9}, {%0,%1,%2,%3};"
        : "+f"(d[0]), "+f"(d[1]), "+f"(d[2]), "+f"(d[3])
        : "r"(a[0]), "r"(a[1]), "r"(a[2]), "r"(a[3]), "r"(b[0]), "r"(b[1]));
}

// one full K=128 pass: acc += A(sA) * W(sB)^T for this warp's 32x64 tile
__device__ __forceinline__ void gemm_pass(
    float acc[2][8][4], uint32_t sA, uint32_t sB,
    int mrow, int ncol, int grp, int thr4)
{
#pragma unroll
    for (int ks = 0; ks < 8; ks++) {
        const int k0 = ks * 16;
        uint32_t afr[2][4];
#pragma unroll
        for (int mt = 0; mt < 2; mt++) {
            int r = mrow + mt * 16 + grp;
            uint32_t base = sA + (uint32_t)(r * LDT + k0 + thr4 * 2) * 2;
            asm volatile("ld.shared.b32 %0, [%1];" : "=r"(afr[mt][0]) : "r"(base));
            asm volatile("ld.shared.b32 %0, [%1];" : "=r"(afr[mt][1]) : "r"(base + 8 * LDT * 2));
            asm volatile("ld.shared.b32 %0, [%1];" : "=r"(afr[mt][2]) : "r"(base + 16));
            asm volatile("ld.shared.b32 %0, [%1];" : "=r"(afr[mt][3]) : "r"(base + 8 * LDT * 2 + 16));
        }
#pragma unroll
        for (int nt = 0; nt < 8; nt++) {
            int n = ncol + nt * 8 + grp;
            uint32_t base = sB + (uint32_t)(n * LDT + k0 + thr4 * 2) * 2;
            uint32_t bfr[2];
            asm volatile("ld.shared.b32 %0, [%1];" : "=r"(bfr[0]) : "r"(base));
            asm volatile("ld.shared.b32 %0, [%1];" : "=r"(bfr[1]) : "r"(base + 16));
#pragma unroll
            for (int mt = 0; mt < 2; mt++)
                mma16816(acc[mt][nt], afr[mt], bfr);
        }
    }
}

__global__ void __launch_bounds__(256, 2)
hmma_gemm(const float* __restrict__ A,
          const __nv_bfloat16* __restrict__ whi,
          const __nv_bfloat16* __restrict__ wlo,
          float* __restrict__ C, int ldc,
          const float* __restrict__ bias)
{
    extern __shared__ char smem[];
    const uint32_t sb = smem_u32(smem);
    const int tid = threadIdx.x;
    const int wid = tid >> 5;
    const int lane = tid & 31;
    const int m0 = blockIdx.y * 128;
    const int n0 = blockIdx.x * 128;

    // ---- Load + split A tile (128 x 128 fp32 -> bf16 hi/lo) ----
#pragma unroll
    for (int it = 0; it < 8; it++) {
        int e = it * 256 + tid;
        int r = e >> 4;
        int k0 = (e & 15) * 8;
        const float4* p = reinterpret_cast<const float4*>(A + (size_t)(m0 + r) * 128 + k0);
        float4 x0 = p[0], x1 = p[1];
        float f[8] = {x0.x, x0.y, x0.z, x0.w, x1.x, x1.y, x1.z, x1.w};
        uint32_t h[4], l[4];
#pragma unroll
        for (int j = 0; j < 4; j++) {
            float a = f[2 * j], b = f[2 * j + 1];
            __nv_bfloat16 ha = __float2bfloat16(a), hb = __float2bfloat16(b);
            float ra = a - __bfloat162float(ha);
            float rb = b - __bfloat162float(hb);
            unsigned short ua = reinterpret_cast<unsigned short&>(ha);
            unsigned short ub = reinterpret_cast<unsigned short&>(hb);
            h[j] = (uint32_t)ua | ((uint32_t)ub << 16);
            l[j] = pack2(ra, rb);
        }
        uint32_t off = (uint32_t)(r * LDT + k0) * 2;
        *reinterpret_cast<uint4*>(smem + SM_AHI + off) = make_uint4(h[0], h[1], h[2], h[3]);
        *reinterpret_cast<uint4*>(smem + SM_ALO + off) = make_uint4(l[0], l[1], l[2], l[3]);
    }
    // ---- Load Whi tile ----
#pragma unroll
    for (int it = 0; it < 8; it++) {
        int e = it * 256 + tid;
        int r = e >> 4;
        int k0 = (e & 15) * 8;
        uint32_t off = (uint32_t)(r * LDT + k0) * 2;
        *reinterpret_cast<uint4*>(smem + SM_WHI + off) =
            *reinterpret_cast<const uint4*>(whi + (size_t)(n0 + r) * 128 + k0);
    }
    __syncthreads();

    const int mrow = (wid & 3) * 32;
    const int ncol = (wid >> 2) * 64;
    const int grp = lane >> 2;
    const int thr4 = lane & 3;

    float acc[2][8][4];
#pragma unroll
    for (int mt = 0; mt < 2; mt++)
#pragma unroll
        for (int nt = 0; nt < 8; nt++)
#pragma unroll
            for (int j = 0; j < 4; j++) acc[mt][nt][j] = 0.f;

    // pass 1: Ahi x Whi ; pass 2: Alo x Whi
    gemm_pass(acc, sb + SM_AHI, sb + SM_WHI, mrow, ncol, grp, thr4);
    gemm_pass(acc, sb + SM_ALO, sb + SM_WHI, mrow, ncol, grp, thr4);
    __syncthreads();   // all reads of Alo done before overwrite

    // ---- Overwrite Alo slot with Wlo ----
#pragma unroll
    for (int it = 0; it < 8; it++) {
        int e = it * 256 + tid;
        int r = e >> 4;
        int k0 = (e & 15) * 8;
        uint32_t off = (uint32_t)(r * LDT + k0) * 2;
        *reinterpret_cast<uint4*>(smem + SM_ALO + off) =
            *reinterpret_cast<const uint4*>(wlo + (size_t)(n0 + r) * 128 + k0);
    }
    __syncthreads();

    // pass 3: Ahi x Wlo
    gemm_pass(acc, sb + SM_AHI, sb + SM_ALO, mrow, ncol, grp, thr4);

    // ---- Epilogue ----
#pragma unroll
    for (int mt = 0; mt < 2; mt++) {
        int r0 = m0 + mrow + mt * 16 + grp;
#pragma unroll
        for (int nt = 0; nt < 8; nt++) {
            int c = n0 + ncol + nt * 8 + thr4 * 2;
            float bx = 0.f, by = 0.f;
            if (bias) { bx = bias[c]; by = bias[c + 1]; }
            float2 v0 = make_float2(acc[mt][nt][0] + bx, acc[mt][nt][1] + by);
            float2 v1 = make_float2(acc[mt][nt][2] + bx, acc[mt][nt][3] + by);
            *reinterpret_cast<float2*>(C + (size_t)r0 * ldc + c) = v0;
            *reinterpret_cast<float2*>(C + (size_t)(r0 + 8) * ldc + c) = v1;
        }
    }
}

// ============================================================================
// Windowed attention (R8, measured-good): one block per (b, window, head).
// ============================================================================
__global__ __launch_bounds__(224) void attn_kernel()
{
    const int idx = blockIdx.x;
    const int h = idx & 3;
    const int g = (idx >> 2) & 63;
    const int b = idx >> 8;
    const int gy = g >> 3, gx = g & 7;

    __shared__ float qs[52][33];
    __shared__ float ks[52][33];
    __shared__ float vs[52][33];
    __shared__ float S[52 * 52];

    const int tid = threadIdx.x;

    for (int l = tid; l < 49 * 32; l += 224) {
        int i = l >> 5, c = l & 31;
        int n = (gy * 7 + i / 7) * 56 + gx * 7 + (i % 7);
        size_t base = ((size_t)b * N_ + n) * 384 + h * 32 + c;
        qs[i][c] = g_qkv[base];
        ks[i][c] = g_qkv[base + 128];
        vs[i][c] = g_qkv[base + 256];
    }
    if (tid < 96) {
        int r = 49 + tid / 32, c = tid & 31;
        qs[r][c] = 0.f; ks[r][c] = 0.f; vs[r][c] = 0.f;
    }
    __syncthreads();

    const float scale = 0.17677669529663687f;   // 32^-0.5

    if (tid < 169) {
        int ti = (tid / 13) * 4, tj = (tid % 13) * 4;
        float acc[4][4];
#pragma unroll
        for (int ii = 0; ii < 4; ii++)
#pragma unroll
            for (int jj = 0; jj < 4; jj++) acc[ii][jj] = 0.f;
#pragma unroll
        for (int c = 0; c < 32; c++) {
            float a[4], bb[4];
#pragma unroll
            for (int ii = 0; ii < 4; ii++) a[ii] = qs[ti + ii][c];
#pragma unroll
            for (int jj = 0; jj < 4; jj++) bb[jj] = ks[tj + jj][c];
#pragma unroll
            for (int ii = 0; ii < 4; ii++)
#pragma unroll
                for (int jj = 0; jj < 4; jj++) acc[ii][jj] += a[ii] * bb[jj];
        }
#pragma unroll
        for (int ii = 0; ii < 4; ii++)
#pragma unroll
            for (int jj = 0; jj < 4; jj++)
                S[(ti + ii) * 52 + tj + jj] = acc[ii][jj] * scale;
    }
    __syncthreads();

    if (tid < 49) {
        float m = -1e30f;
        for (int j = 0; j < 49; j++) m = fmaxf(m, S[tid * 52 + j]);
        float s = 0.f;
        for (int j = 0; j < 49; j++) {
            float e = __expf(S[tid * 52 + j] - m);
            S[tid * 52 + j] = e;
            s += e;
        }
        float inv = __fdividef(1.f, s);
        for (int j = 0; j < 49; j++) S[tid * 52 + j] *= inv;
    }
    __syncthreads();

    if (tid < 104) {
        int ti = (tid >> 3) * 4, td = (tid & 7) * 4;
        float acc[4][4];
#pragma unroll
        for (int ii = 0; ii < 4; ii++)
#pragma unroll
            for (int dd = 0; dd < 4; dd++) acc[ii][dd] = 0.f;
        for (int j = 0; j < 49; j++) {
            float p[4], v[4];
#pragma unroll
            for (int ii = 0; ii < 4; ii++) p[ii] = S[(ti + ii) * 52 + j];
#pragma unroll
            for (int dd = 0; dd < 4; dd++) v[dd] = vs[j][td + dd];
#pragma unroll
            for (int ii = 0; ii < 4; ii++)
#pragma unroll
                for (int dd = 0; dd < 4; dd++) acc[ii][dd] += p[ii] * v[dd];
        }
#pragma unroll
        for (int ii = 0; ii < 4; ii++) {
            int i = ti + ii;
            if (i < 49) {
                int n = (gy * 7 + i / 7) * 56 + gx * 7 + (i % 7);
                size_t ob = ((size_t)b * N_ + n) * 128 + h * 32 + td;
#pragma unroll
                for (int dd = 0; dd < 4; dd++) g_attn[ob + dd] = acc[ii][dd];
            }
        }
    }
}

// ============================================================================
// Tiled depthwise 3x3 conv on V + bias, float4 (R8, measured-good).
// ============================================================================
#define CONV_SMEM (10 * 58 * 32 * 4)   // 74240 B

__global__ __launch_bounds__(256) void conv_tiled(
    const float* __restrict__ w_lim, const float* __restrict__ b_lim)
{
    extern __shared__ float vsm[];     // [10 rows][58 x][32 ch]
    const int yt = blockIdx.x;         // 0..6
    const int c0 = blockIdx.y * 32;    // channel split
    const int b  = blockIdx.z;
    const int y0 = yt * 8;
    const int tid = threadIdx.x;

    for (int l = tid; l < 640; l += 256) {
        int r = l / 64;
        int side = (l >> 5) & 1;
        int c = l & 31;
        vsm[(r * 58 + (side ? 57 : 0)) * 32 + c] = 0.f;
    }
    for (int l = tid; l < 10 * 56 * 32; l += 256) {
        int c = l & 31;
        int x = (l >> 5) % 56;
        int r = (l >> 5) / 56;
        int Y = y0 + r - 1;
        float v = 0.f;
        if ((unsigned)Y < 56u)
            v = g_qkv[((size_t)b * N_ + Y * 56 + x) * 384 + 256 + c0 + c];
        vsm[(r * 58 + x + 1) * 32 + c] = v;
    }

    const int c4 = tid & 7;
    const int xq = tid >> 3;
    const int ch = c4 * 4;

    float4 w4[9];
#pragma unroll
    for (int t = 0; t < 9; t++) {
        w4[t].x = w_lim[(c0 + ch + 0) * 9 + t];
        w4[t].y = w_lim[(c0 + ch + 1) * 9 + t];
        w4[t].z = w_lim[(c0 + ch + 2) * 9 + t];
        w4[t].w = w_lim[(c0 + ch + 3) * 9 + t];
    }
    const float4 bias4 = *reinterpret_cast<const float4*>(b_lim + c0 + ch);

    __syncthreads();

    const float4* vsm4 = reinterpret_cast<const float4*>(vsm);

#pragma unroll
    for (int p = 0; p < 2; p++) {
        const int x = xq + 32 * p;
        if (x >= 56) break;
#pragma unroll
        for (int r = 0; r < 8; r++) {
            float4 acc = bias4;
#pragma unroll
            for (int dy = 0; dy < 3; dy++)
#pragma unroll
                for (int dx = 0; dx < 3; dx++) {
                    float4 v = vsm4[((r + dy) * 58 + x + dx) * 8 + c4];
                    float4 w = w4[dy * 3 + dx];
                    acc.x += w.x * v.x;
                    acc.y += w.y * v.y;
                    acc.z += w.z * v.z;
                    acc.w += w.w * v.w;
                }
            float4* ap = reinterpret_cast<float4*>(
                &g_attn[((size_t)b * N_ + (y0 + r) * 56 + x) * 128 + c0 + ch]);
            float4 o = *ap;
            o.x += acc.x; o.y += acc.y; o.z += acc.z; o.w += acc.w;
            *ap = o;
        }
    }
}

// ============================================================================
extern "C" void kernel_launch(void* const* d_in, const int* in_sizes, int n_in,
                              void* d_out, int out_size)
{
    const float* x      = (const float*)d_in[0];
    const float* w_qkv  = (const float*)d_in[1];
    const float* w_lim  = (const float*)d_in[2];
    const float* b_lim  = (const float*)d_in[3];
    const float* w_proj = (const float*)d_in[4];
    const float* b_proj = (const float*)d_in[5];
    float* out = (float*)d_out;

    float *qkv_ptr, *attn_ptr;
    __nv_bfloat16 *wh_ptr, *wl_ptr;
    cudaGetSymbolAddress((void**)&qkv_ptr,  g_qkv);
    cudaGetSymbolAddress((void**)&attn_ptr, g_attn);
    cudaGetSymbolAddress((void**)&wh_ptr,   g_wh);
    cudaGetSymbolAddress((void**)&wl_ptr,   g_wl);

    cudaFuncSetAttribute(hmma_gemm, cudaFuncAttributeMaxDynamicSharedMemorySize, SM_BYTES);
    cudaFuncSetAttribute(conv_tiled, cudaFuncAttributeMaxDynamicSharedMemorySize, CONV_SMEM);

    // 0) split weights into bf16 hi/lo
    prep_weights<<<(512 * 128 + 255) / 256, 256>>>(w_qkv, w_proj);

    // 1) qkv = x @ w_qkv^T   (2D grid; x re-reads are L2 hits)
    hmma_gemm<<<dim3(3, M_TOT / 128), 256, SM_BYTES>>>(x, wh_ptr, wl_ptr, qkv_ptr, 384, nullptr);

    // 2) windowed attention
    attn_kernel<<<B_ * 64 * NHEAD, 224>>>();

    // 3) tiled depthwise conv(v) + b_lim into g_attn (float4)
    conv_tiled<<<dim3(7, 4, B_), 256, CONV_SMEM>>>(w_lim, b_lim);

    // 4) out = g_attn @ w_proj^T + b_proj
    hmma_gemm<<<dim3(1, M_TOT / 128), 256, SM_BYTES>>>(attn_ptr, wh_ptr + 384 * 128,
                                                       wl_ptr + 384 * 128, out, 128, b_proj);
}

// round 11
// speedup vs baseline: 1.0712x; 1.0507x over previous
#include <cuda_runtime.h>
#include <cuda_bf16.h>
#include <cstdint>

#define B_    64
#define Himg  56
#define Wimg  56
#define C_    128
#define N_    3136
#define NHEAD 4
#define M_TOT (B_ * N_)     // 200704

// Scratch (allocation-free rule: device globals)
__device__ float g_qkv[(size_t)M_TOT * 384];           // 308 MB
__device__ float g_attn[(size_t)M_TOT * C_];           // 103 MB
__device__ __nv_bfloat16 g_wh[512 * 128];              // weights hi (qkv rows 0..383, proj 384..511)
__device__ __nv_bfloat16 g_wl[512 * 128];              // weights lo

// ============================================================================
// Weight split prep: fp32 -> bf16 hi/lo
// ============================================================================
__global__ void prep_weights(const float* __restrict__ w_qkv,
                             const float* __restrict__ w_proj)
{
    int idx = blockIdx.x * 256 + threadIdx.x;
    if (idx >= 512 * 128) return;
    float w = (idx < 384 * 128) ? w_qkv[idx] : w_proj[idx - 384 * 128];
    __nv_bfloat16 hi = __float2bfloat16(w);
    float r = w - __bfloat162float(hi);
    g_wh[idx] = hi;
    g_wl[idx] = __float2bfloat16(r);
}

// ============================================================================
// HMMA GEMM: C[M, ldc] = A[M,128] @ W[N,128]^T (+bias), 3-term bf16 split.
// CTA tile 128x128, 512 threads = 16 warps (4x4), warp tile 32x32.
// Fragments via ldmatrix.x4. A loaded+split once; loops over ntiles W tiles.
// ============================================================================
#define LDT 136                      // padded row stride in bf16 elements
#define TILE_B (128 * LDT * 2)       // 34816 B per tile
#define SM_AHI 0
#define SM_ALO (TILE_B)
#define SM_WHI (2 * TILE_B)
#define SM_WLO (3 * TILE_B)
#define SM_BYTES (4 * TILE_B)        // 139264 B -> 1 CTA/SM, 16 warps

__device__ __forceinline__ uint32_t smem_u32(const void* p) {
    uint32_t a;
    asm("{ .reg .u64 t; cvta.to.shared.u64 t, %1; cvt.u32.u64 %0, t; }" : "=r"(a) : "l"(p));
    return a;
}

__device__ __forceinline__ uint32_t pack2(float a, float b) {
    __nv_bfloat16 ha = __float2bfloat16(a), hb = __float2bfloat16(b);
    unsigned short ua = reinterpret_cast<unsigned short&>(ha);
    unsigned short ub = reinterpret_cast<unsigned short&>(hb);
    return (uint32_t)ua | ((uint32_t)ub << 16);
}

__device__ __forceinline__ void mma16816(float* d, const uint32_t* a,
                                         uint32_t b0, uint32_t b1) {
    asm volatile(
        "mma.sync.aligned.m16n8k16.row.col.f32.bf16.bf16.f32 "
        "{%0,%1,%2,%3}, {%4,%5,%6,%7}, {%8,%9}, {%0,%1,%2,%3};"
        : "+f"(d[0]), "+f"(d[1]), "+f"(d[2]), "+f"(d[3])
        : "r"(a[0]), "r"(a[1]), "r"(a[2]), "r"(a[3]), "r"(b0), "r"(b1));
}

#define LDMX4(r, addr) \
    asm volatile("ldmatrix.sync.aligned.m8n8.x4.shared.b16 {%0,%1,%2,%3}, [%4];" \
        : "=r"((r)[0]), "=r"((r)[1]), "=r"((r)[2]), "=r"((r)[3]) : "r"(addr))

// one full K=128 pass: acc += A(sA) * W(sB)^T for this warp's 32x32 tile.
// aoff/boff are lane-dependent byte offsets within a 16x16 (bf16) ldmatrix block.
__device__ __forceinline__ void gemm_pass(
    float acc[2][4][4], uint32_t sA, uint32_t sB,
    uint32_t aoff, uint32_t boff)
{
#pragma unroll
    for (int ks = 0; ks < 8; ks++) {
        const uint32_t kb = (uint32_t)(ks * 16 * 2);   // k-step byte offset
        uint32_t af[2][4];
#pragma unroll
        for (int mt = 0; mt < 2; mt++)
            LDMX4(af[mt], sA + aoff + kb + (uint32_t)(mt * 16 * LDT * 2));
        uint32_t bf[2][4];
#pragma unroll
        for (int p = 0; p < 2; p++)
            LDMX4(bf[p], sB + boff + kb + (uint32_t)(p * 16 * LDT * 2));
#pragma unroll
        for (int nt = 0; nt < 4; nt++) {
            uint32_t b0 = bf[nt >> 1][(nt & 1) * 2];
            uint32_t b1 = bf[nt >> 1][(nt & 1) * 2 + 1];
#pragma unroll
            for (int mt = 0; mt < 2; mt++)
                mma16816(acc[mt][nt], af[mt], b0, b1);
        }
    }
}

__global__ void __launch_bounds__(512)
hmma_gemm(const float* __restrict__ A,
          const __nv_bfloat16* __restrict__ whi,
          const __nv_bfloat16* __restrict__ wlo,
          float* __restrict__ C, int ldc, int ntiles,
          const float* __restrict__ bias)
{
    extern __shared__ char smem[];
    const uint32_t sb = smem_u32(smem);
    const int tid = threadIdx.x;
    const int wid = tid >> 5;
    const int lane = tid & 31;
    const int m0 = blockIdx.x * 128;

    // ---- Load + split A tile (128 x 128 fp32 -> bf16 hi/lo), once ----
#pragma unroll
    for (int it = 0; it < 4; it++) {
        int e = it * 512 + tid;          // 2048 chunks of 8 k-cols
        int r = e >> 4;
        int k0 = (e & 15) * 8;
        const float4* p = reinterpret_cast<const float4*>(A + (size_t)(m0 + r) * 128 + k0);
        float4 x0 = p[0], x1 = p[1];
        float f[8] = {x0.x, x0.y, x0.z, x0.w, x1.x, x1.y, x1.z, x1.w};
        uint32_t h[4], l[4];
#pragma unroll
        for (int j = 0; j < 4; j++) {
            float a = f[2 * j], b = f[2 * j + 1];
            __nv_bfloat16 ha = __float2bfloat16(a), hb = __float2bfloat16(b);
            float ra = a - __bfloat162float(ha);
            float rb = b - __bfloat162float(hb);
            unsigned short ua = reinterpret_cast<unsigned short&>(ha);
            unsigned short ub = reinterpret_cast<unsigned short&>(hb);
            h[j] = (uint32_t)ua | ((uint32_t)ub << 16);
            l[j] = pack2(ra, rb);
        }
        uint32_t off = (uint32_t)(r * LDT + k0) * 2;
        *reinterpret_cast<uint4*>(smem + SM_AHI + off) = make_uint4(h[0], h[1], h[2], h[3]);
        *reinterpret_cast<uint4*>(smem + SM_ALO + off) = make_uint4(l[0], l[1], l[2], l[3]);
    }

    // warp layout: 4 warps along M x 4 along N; warp tile 32x32
    const int mrow = (wid & 3) * 32;
    const int ncol = (wid >> 2) * 32;

    // ldmatrix lane addressing (t = lane>>3 selects the 8x8 tile)
    const int t = lane >> 3, lr = lane & 7;
    // A x4 tiles: t0 rows0-7@k0, t1 rows8-15@k0, t2 rows0-7@k8, t3 rows8-15@k8
    const uint32_t aoff =
        (uint32_t)(((mrow + (t & 1) * 8 + lr) * LDT) * 2 + (t >> 1) * 16);
    // B x4 tiles: t0 n0-7@k0, t1 n0-7@k8, t2 n8-15@k0, t3 n8-15@k8
    const uint32_t boff =
        (uint32_t)(((ncol + (t >> 1) * 8 + lr) * LDT) * 2 + (t & 1) * 16);

    for (int nt = 0; nt < ntiles; nt++) {
        const int n0 = nt * 128;
        // ---- Load W tiles for this n block ----
#pragma unroll
        for (int it = 0; it < 4; it++) {
            int e = it * 512 + tid;
            int r = e >> 4;
            int k0 = (e & 15) * 8;
            uint32_t off = (uint32_t)(r * LDT + k0) * 2;
            *reinterpret_cast<uint4*>(smem + SM_WHI + off) =
                *reinterpret_cast<const uint4*>(whi + (size_t)(n0 + r) * 128 + k0);
            *reinterpret_cast<uint4*>(smem + SM_WLO + off) =
                *reinterpret_cast<const uint4*>(wlo + (size_t)(n0 + r) * 128 + k0);
        }
        __syncthreads();

        float acc[2][4][4];
#pragma unroll
        for (int mt = 0; mt < 2; mt++)
#pragma unroll
            for (int ntt = 0; ntt < 4; ntt++)
#pragma unroll
                for (int j = 0; j < 4; j++) acc[mt][ntt][j] = 0.f;

        // same pass order as R8: hi*hi, hi*lo? -> R8 order: hi*hi, Ahi*Wlo? No:
        // R8: pass0 Ahi/Whi, pass1 Ahi? (pass==2?ALO:AHI, pass==1?WLO:WHI)
        //     => pass0: Ahi x Whi, pass1: Ahi x Wlo, pass2: Alo x Whi
        gemm_pass(acc, sb + SM_AHI, sb + SM_WHI, aoff, boff);
        gemm_pass(acc, sb + SM_AHI, sb + SM_WLO, aoff, boff);
        gemm_pass(acc, sb + SM_ALO, sb + SM_WHI, aoff, boff);

        // ---- Epilogue ----
        const int grp = lane >> 2;
        const int thr4 = lane & 3;
#pragma unroll
        for (int mt = 0; mt < 2; mt++) {
            int r0 = m0 + mrow + mt * 16 + grp;
#pragma unroll
            for (int ntt = 0; ntt < 4; ntt++) {
                int c = n0 + ncol + ntt * 8 + thr4 * 2;
                float bx = 0.f, by = 0.f;
                if (bias) { bx = bias[c]; by = bias[c + 1]; }
                float2 v0 = make_float2(acc[mt][ntt][0] + bx, acc[mt][ntt][1] + by);
                float2 v1 = make_float2(acc[mt][ntt][2] + bx, acc[mt][ntt][3] + by);
                *reinterpret_cast<float2*>(C + (size_t)r0 * ldc + c) = v0;
                *reinterpret_cast<float2*>(C + (size_t)(r0 + 8) * ldc + c) = v1;
            }
        }
        __syncthreads();
    }
}

// ============================================================================
// Windowed attention (R8, measured-good): one block per (b, window, head).
// ============================================================================
__global__ __launch_bounds__(224) void attn_kernel()
{
    const int idx = blockIdx.x;
    const int h = idx & 3;
    const int g = (idx >> 2) & 63;
    const int b = idx >> 8;
    const int gy = g >> 3, gx = g & 7;

    __shared__ float qs[52][33];
    __shared__ float ks[52][33];
    __shared__ float vs[52][33];
    __shared__ float S[52 * 52];

    const int tid = threadIdx.x;

    for (int l = tid; l < 49 * 32; l += 224) {
        int i = l >> 5, c = l & 31;
        int n = (gy * 7 + i / 7) * 56 + gx * 7 + (i % 7);
        size_t base = ((size_t)b * N_ + n) * 384 + h * 32 + c;
        qs[i][c] = g_qkv[base];
        ks[i][c] = g_qkv[base + 128];
        vs[i][c] = g_qkv[base + 256];
    }
    if (tid < 96) {
        int r = 49 + tid / 32, c = tid & 31;
        qs[r][c] = 0.f; ks[r][c] = 0.f; vs[r][c] = 0.f;
    }
    __syncthreads();

    const float scale = 0.17677669529663687f;   // 32^-0.5

    if (tid < 169) {
        int ti = (tid / 13) * 4, tj = (tid % 13) * 4;
        float acc[4][4];
#pragma unroll
        for (int ii = 0; ii < 4; ii++)
#pragma unroll
            for (int jj = 0; jj < 4; jj++) acc[ii][jj] = 0.f;
#pragma unroll
        for (int c = 0; c < 32; c++) {
            float a[4], bb[4];
#pragma unroll
            for (int ii = 0; ii < 4; ii++) a[ii] = qs[ti + ii][c];
#pragma unroll
            for (int jj = 0; jj < 4; jj++) bb[jj] = ks[tj + jj][c];
#pragma unroll
            for (int ii = 0; ii < 4; ii++)
#pragma unroll
                for (int jj = 0; jj < 4; jj++) acc[ii][jj] += a[ii] * bb[jj];
        }
#pragma unroll
        for (int ii = 0; ii < 4; ii++)
#pragma unroll
            for (int jj = 0; jj < 4; jj++)
                S[(ti + ii) * 52 + tj + jj] = acc[ii][jj] * scale;
    }
    __syncthreads();

    if (tid < 49) {
        float m = -1e30f;
        for (int j = 0; j < 49; j++) m = fmaxf(m, S[tid * 52 + j]);
        float s = 0.f;
        for (int j = 0; j < 49; j++) {
            float e = __expf(S[tid * 52 + j] - m);
            S[tid * 52 + j] = e;
            s += e;
        }
        float inv = __fdividef(1.f, s);
        for (int j = 0; j < 49; j++) S[tid * 52 + j] *= inv;
    }
    __syncthreads();

    if (tid < 104) {
        int ti = (tid >> 3) * 4, td = (tid & 7) * 4;
        float acc[4][4];
#pragma unroll
        for (int ii = 0; ii < 4; ii++)
#pragma unroll
            for (int dd = 0; dd < 4; dd++) acc[ii][dd] = 0.f;
        for (int j = 0; j < 49; j++) {
            float p[4], v[4];
#pragma unroll
            for (int ii = 0; ii < 4; ii++) p[ii] = S[(ti + ii) * 52 + j];
#pragma unroll
            for (int dd = 0; dd < 4; dd++) v[dd] = vs[j][td + dd];
#pragma unroll
            for (int ii = 0; ii < 4; ii++)
#pragma unroll
                for (int dd = 0; dd < 4; dd++) acc[ii][dd] += p[ii] * v[dd];
        }
#pragma unroll
        for (int ii = 0; ii < 4; ii++) {
            int i = ti + ii;
            if (i < 49) {
                int n = (gy * 7 + i / 7) * 56 + gx * 7 + (i % 7);
                size_t ob = ((size_t)b * N_ + n) * 128 + h * 32 + td;
#pragma unroll
                for (int dd = 0; dd < 4; dd++) g_attn[ob + dd] = acc[ii][dd];
            }
        }
    }
}

// ============================================================================
// Tiled depthwise 3x3 conv on V + bias, float4 (R8, measured-good).
// ============================================================================
#define CONV_SMEM (10 * 58 * 32 * 4)   // 74240 B

__global__ __launch_bounds__(256) void conv_tiled(
    const float* __restrict__ w_lim, const float* __restrict__ b_lim)
{
    extern __shared__ float vsm[];     // [10 rows][58 x][32 ch]
    const int yt = blockIdx.x;         // 0..6
    const int c0 = blockIdx.y * 32;    // channel split
    const int b  = blockIdx.z;
    const int y0 = yt * 8;
    const int tid = threadIdx.x;

    for (int l = tid; l < 640; l += 256) {
        int r = l / 64;
        int side = (l >> 5) & 1;
        int c = l & 31;
        vsm[(r * 58 + (side ? 57 : 0)) * 32 + c] = 0.f;
    }
    for (int l = tid; l < 10 * 56 * 32; l += 256) {
        int c = l & 31;
        int x = (l >> 5) % 56;
        int r = (l >> 5) / 56;
        int Y = y0 + r - 1;
        float v = 0.f;
        if ((unsigned)Y < 56u)
            v = g_qkv[((size_t)b * N_ + Y * 56 + x) * 384 + 256 + c0 + c];
        vsm[(r * 58 + x + 1) * 32 + c] = v;
    }

    const int c4 = tid & 7;
    const int xq = tid >> 3;
    const int ch = c4 * 4;

    float4 w4[9];
#pragma unroll
    for (int t = 0; t < 9; t++) {
        w4[t].x = w_lim[(c0 + ch + 0) * 9 + t];
        w4[t].y = w_lim[(c0 + ch + 1) * 9 + t];
        w4[t].z = w_lim[(c0 + ch + 2) * 9 + t];
        w4[t].w = w_lim[(c0 + ch + 3) * 9 + t];
    }
    const float4 bias4 = *reinterpret_cast<const float4*>(b_lim + c0 + ch);

    __syncthreads();

    const float4* vsm4 = reinterpret_cast<const float4*>(vsm);

#pragma unroll
    for (int p = 0; p < 2; p++) {
        const int x = xq + 32 * p;
        if (x >= 56) break;
#pragma unroll
        for (int r = 0; r < 8; r++) {
            float4 acc = bias4;
#pragma unroll
            for (int dy = 0; dy < 3; dy++)
#pragma unroll
                for (int dx = 0; dx < 3; dx++) {
                    float4 v = vsm4[((r + dy) * 58 + x + dx) * 8 + c4];
                    float4 w = w4[dy * 3 + dx];
                    acc.x += w.x * v.x;
                    acc.y += w.y * v.y;
                    acc.z += w.z * v.z;
                    acc.w += w.w * v.w;
                }
            float4* ap = reinterpret_cast<float4*>(
                &g_attn[((size_t)b * N_ + (y0 + r) * 56 + x) * 128 + c0 + ch]);
            float4 o = *ap;
            o.x += acc.x; o.y += acc.y; o.z += acc.z; o.w += acc.w;
            *ap = o;
        }
    }
}

// ============================================================================
extern "C" void kernel_launch(void* const* d_in, const int* in_sizes, int n_in,
                              void* d_out, int out_size)
{
    const float* x      = (const float*)d_in[0];
    const float* w_qkv  = (const float*)d_in[1];
    const float* w_lim  = (const float*)d_in[2];
    const float* b_lim  = (const float*)d_in[3];
    const float* w_proj = (const float*)d_in[4];
    const float* b_proj = (const float*)d_in[5];
    float* out = (float*)d_out;

    float *qkv_ptr, *attn_ptr;
    __nv_bfloat16 *wh_ptr, *wl_ptr;
    cudaGetSymbolAddress((void**)&qkv_ptr,  g_qkv);
    cudaGetSymbolAddress((void**)&attn_ptr, g_attn);
    cudaGetSymbolAddress((void**)&wh_ptr,   g_wh);
    cudaGetSymbolAddress((void**)&wl_ptr,   g_wl);

    cudaFuncSetAttribute(hmma_gemm, cudaFuncAttributeMaxDynamicSharedMemorySize, SM_BYTES);
    cudaFuncSetAttribute(conv_tiled, cudaFuncAttributeMaxDynamicSharedMemorySize, CONV_SMEM);

    // 0) split weights into bf16 hi/lo
    prep_weights<<<(512 * 128 + 255) / 256, 256>>>(w_qkv, w_proj);

    // 1) qkv = x @ w_qkv^T  (A loaded+split once, 3 W tiles)
    hmma_gemm<<<M_TOT / 128, 512, SM_BYTES>>>(x, wh_ptr, wl_ptr, qkv_ptr, 384, 3, nullptr);

    // 2) windowed attention
    attn_kernel<<<B_ * 64 * NHEAD, 224>>>();

    // 3) tiled depthwise conv(v) + b_lim into g_attn (float4)
    conv_tiled<<<dim3(7, 4, B_), 256, CONV_SMEM>>>(w_lim, b_lim);

    // 4) out = g_attn @ w_proj^T + b_proj
    hmma_gemm<<<M_TOT / 128, 512, SM_BYTES>>>(attn_ptr, wh_ptr + 384 * 128,
                                              wl_ptr + 384 * 128, out, 128, 1, b_proj);
}

// round 12
// speedup vs baseline: 1.1873x; 1.1083x over previous
#include <cuda_runtime.h>
#include <cuda_bf16.h>
#include <cstdint>

#define B_    64
#define Himg  56
#define Wimg  56
#define C_    128
#define N_    3136
#define NHEAD 4
#define M_TOT (B_ * N_)     // 200704

// Scratch (allocation-free rule: device globals)
__device__ float g_qkv[(size_t)M_TOT * 384];           // 308 MB
__device__ float g_attn[(size_t)M_TOT * C_];           // 103 MB
__device__ __nv_bfloat16 g_wh[512 * 128];              // weights hi (qkv rows 0..383, proj 384..511)
__device__ __nv_bfloat16 g_wl[512 * 128];              // weights lo

// ============================================================================
// Weight split prep: fp32 -> bf16 hi/lo
// ============================================================================
__global__ void prep_weights(const float* __restrict__ w_qkv,
                             const float* __restrict__ w_proj)
{
    int idx = blockIdx.x * 256 + threadIdx.x;
    if (idx >= 512 * 128) return;
    float w = (idx < 384 * 128) ? w_qkv[idx] : w_proj[idx - 384 * 128];
    __nv_bfloat16 hi = __float2bfloat16(w);
    float r = w - __bfloat162float(hi);
    g_wh[idx] = hi;
    g_wl[idx] = __float2bfloat16(r);
}

// ============================================================================
// HMMA GEMM: C[M, ldc] = A[M,128] @ W[N,128]^T (+bias), 3-term bf16 split.
// R8 shape (measured-best): tile 128x128, 256 threads (8 warps 4x2),
// warp tile 32x64, A-reuse ntiles loop. NEW: the 3 split passes are fused
// into ONE k-loop (48 LDS per 24 MMAs instead of 72; 3x MMA ILP).
// ============================================================================
#define LDT 136                      // padded row stride in bf16 elements
#define TILE_B (128 * LDT * 2)       // 34816 B per tile
#define SM_AHI 0
#define SM_ALO (TILE_B)
#define SM_WHI (2 * TILE_B)
#define SM_WLO (3 * TILE_B)
#define SM_BYTES (4 * TILE_B)

__device__ __forceinline__ uint32_t smem_u32(const void* p) {
    uint32_t a;
    asm("{ .reg .u64 t; cvta.to.shared.u64 t, %1; cvt.u32.u64 %0, t; }" : "=r"(a) : "l"(p));
    return a;
}

__device__ __forceinline__ uint32_t pack2(float a, float b) {
    __nv_bfloat16 ha = __float2bfloat16(a), hb = __float2bfloat16(b);
    unsigned short ua = reinterpret_cast<unsigned short&>(ha);
    unsigned short ub = reinterpret_cast<unsigned short&>(hb);
    return (uint32_t)ua | ((uint32_t)ub << 16);
}

__device__ __forceinline__ void mma16816(float* d, const uint32_t* a, const uint32_t* b) {
    asm volatile(
        "mma.sync.aligned.m16n8k16.row.col.f32.bf16.bf16.f32 "
        "{%0,%1,%2,%3}, {%4,%5,%6,%7}, {%8,%9}, {%0,%1,%2,%3};"
        : "+f"(d[0]), "+f"(d[1]), "+f"(d[2]), "+f"(d[3])
        : "r"(a[0]), "r"(a[1]), "r"(a[2]), "r"(a[3]), "r"(b[0]), "r"(b[1]));
}

__global__ void __launch_bounds__(256)
hmma_gemm(const float* __restrict__ A,
          const __nv_bfloat16* __restrict__ whi,
          const __nv_bfloat16* __restrict__ wlo,
          float* __restrict__ C, int ldc, int ntiles,
          const float* __restrict__ bias)
{
    extern __shared__ char smem[];
    const uint32_t sb = smem_u32(smem);
    const int tid = threadIdx.x;
    const int wid = tid >> 5;
    const int lane = tid & 31;
    const int m0 = blockIdx.x * 128;

    // ---- Load + split A tile (128 x 128 fp32 -> bf16 hi/lo), once ----
#pragma unroll
    for (int it = 0; it < 8; it++) {
        int e = it * 256 + tid;
        int r = e >> 4;
        int k0 = (e & 15) * 8;
        const float4* p = reinterpret_cast<const float4*>(A + (size_t)(m0 + r) * 128 + k0);
        float4 x0 = p[0], x1 = p[1];
        float f[8] = {x0.x, x0.y, x0.z, x0.w, x1.x, x1.y, x1.z, x1.w};
        uint32_t h[4], l[4];
#pragma unroll
        for (int j = 0; j < 4; j++) {
            float a = f[2 * j], b = f[2 * j + 1];
            __nv_bfloat16 ha = __float2bfloat16(a), hb = __float2bfloat16(b);
            float ra = a - __bfloat162float(ha);
            float rb = b - __bfloat162float(hb);
            unsigned short ua = reinterpret_cast<unsigned short&>(ha);
            unsigned short ub = reinterpret_cast<unsigned short&>(hb);
            h[j] = (uint32_t)ua | ((uint32_t)ub << 16);
            l[j] = pack2(ra, rb);
        }
        uint32_t off = (uint32_t)(r * LDT + k0) * 2;
        *reinterpret_cast<uint4*>(smem + SM_AHI + off) = make_uint4(h[0], h[1], h[2], h[3]);
        *reinterpret_cast<uint4*>(smem + SM_ALO + off) = make_uint4(l[0], l[1], l[2], l[3]);
    }

    const int mrow = (wid & 3) * 32;
    const int ncol = (wid >> 2) * 64;
    const int grp = lane >> 2;
    const int thr4 = lane & 3;

    for (int nt = 0; nt < ntiles; nt++) {
        const int n0 = nt * 128;
        // ---- Load W tiles for this n block ----
#pragma unroll
        for (int it = 0; it < 8; it++) {
            int e = it * 256 + tid;
            int r = e >> 4;
            int k0 = (e & 15) * 8;
            uint32_t off = (uint32_t)(r * LDT + k0) * 2;
            *reinterpret_cast<uint4*>(smem + SM_WHI + off) =
                *reinterpret_cast<const uint4*>(whi + (size_t)(n0 + r) * 128 + k0);
            *reinterpret_cast<uint4*>(smem + SM_WLO + off) =
                *reinterpret_cast<const uint4*>(wlo + (size_t)(n0 + r) * 128 + k0);
        }
        __syncthreads();

        float acc[2][8][4];
#pragma unroll
        for (int mt = 0; mt < 2; mt++)
#pragma unroll
            for (int ntt = 0; ntt < 8; ntt++)
#pragma unroll
                for (int j = 0; j < 4; j++) acc[mt][ntt][j] = 0.f;

        // ---- FUSED 3-stream k-loop: acc += Ahi*Whi + Ahi*Wlo + Alo*Whi ----
#pragma unroll
        for (int ks = 0; ks < 8; ks++) {
            const int k0 = ks * 16;
            uint32_t ah[2][4], al[2][4];
#pragma unroll
            for (int mt = 0; mt < 2; mt++) {
                int r = mrow + mt * 16 + grp;
                uint32_t bh = sb + SM_AHI + (uint32_t)(r * LDT + k0 + thr4 * 2) * 2;
                uint32_t bl = sb + SM_ALO + (uint32_t)(r * LDT + k0 + thr4 * 2) * 2;
                asm volatile("ld.shared.b32 %0, [%1];" : "=r"(ah[mt][0]) : "r"(bh));
                asm volatile("ld.shared.b32 %0, [%1];" : "=r"(ah[mt][1]) : "r"(bh + 8 * LDT * 2));
                asm volatile("ld.shared.b32 %0, [%1];" : "=r"(ah[mt][2]) : "r"(bh + 16));
                asm volatile("ld.shared.b32 %0, [%1];" : "=r"(ah[mt][3]) : "r"(bh + 8 * LDT * 2 + 16));
                asm volatile("ld.shared.b32 %0, [%1];" : "=r"(al[mt][0]) : "r"(bl));
                asm volatile("ld.shared.b32 %0, [%1];" : "=r"(al[mt][1]) : "r"(bl + 8 * LDT * 2));
                asm volatile("ld.shared.b32 %0, [%1];" : "=r"(al[mt][2]) : "r"(bl + 16));
                asm volatile("ld.shared.b32 %0, [%1];" : "=r"(al[mt][3]) : "r"(bl + 8 * LDT * 2 + 16));
            }
#pragma unroll
            for (int ntt = 0; ntt < 8; ntt++) {
                int n = ncol + ntt * 8 + grp;
                uint32_t bh = sb + SM_WHI + (uint32_t)(n * LDT + k0 + thr4 * 2) * 2;
                uint32_t bl = sb + SM_WLO + (uint32_t)(n * LDT + k0 + thr4 * 2) * 2;
                uint32_t wh[2], wl2[2];
                asm volatile("ld.shared.b32 %0, [%1];" : "=r"(wh[0]) : "r"(bh));
                asm volatile("ld.shared.b32 %0, [%1];" : "=r"(wh[1]) : "r"(bh + 16));
                asm volatile("ld.shared.b32 %0, [%1];" : "=r"(wl2[0]) : "r"(bl));
                asm volatile("ld.shared.b32 %0, [%1];" : "=r"(wl2[1]) : "r"(bl + 16));
#pragma unroll
                for (int mt = 0; mt < 2; mt++) {
                    mma16816(acc[mt][ntt], ah[mt], wh);
                    mma16816(acc[mt][ntt], ah[mt], wl2);
                    mma16816(acc[mt][ntt], al[mt], wh);
                }
            }
        }

        // ---- Epilogue ----
#pragma unroll
        for (int mt = 0; mt < 2; mt++) {
            int r0 = m0 + mrow + mt * 16 + grp;
#pragma unroll
            for (int ntt = 0; ntt < 8; ntt++) {
                int c = n0 + ncol + ntt * 8 + thr4 * 2;
                float bx = 0.f, by = 0.f;
                if (bias) { bx = bias[c]; by = bias[c + 1]; }
                float2 v0 = make_float2(acc[mt][ntt][0] + bx, acc[mt][ntt][1] + by);
                float2 v1 = make_float2(acc[mt][ntt][2] + bx, acc[mt][ntt][3] + by);
                *reinterpret_cast<float2*>(C + (size_t)r0 * ldc + c) = v0;
                *reinterpret_cast<float2*>(C + (size_t)(r0 + 8) * ldc + c) = v1;
            }
        }
        __syncthreads();
    }
}

// ============================================================================
// Windowed attention: one block per (b, window, head). 224 threads.
// Phase 3 rebalanced: 200 threads x 2x4 tiles (was 104 x 4x4).
// ============================================================================
__global__ __launch_bounds__(224) void attn_kernel()
{
    const int idx = blockIdx.x;
    const int h = idx & 3;
    const int g = (idx >> 2) & 63;
    const int b = idx >> 8;
    const int gy = g >> 3, gx = g & 7;

    __shared__ float qs[52][33];
    __shared__ float ks[52][33];
    __shared__ float vs[52][33];
    __shared__ float S[52 * 52];

    const int tid = threadIdx.x;

    for (int l = tid; l < 49 * 32; l += 224) {
        int i = l >> 5, c = l & 31;
        int n = (gy * 7 + i / 7) * 56 + gx * 7 + (i % 7);
        size_t base = ((size_t)b * N_ + n) * 384 + h * 32 + c;
        qs[i][c] = g_qkv[base];
        ks[i][c] = g_qkv[base + 128];
        vs[i][c] = g_qkv[base + 256];
    }
    if (tid < 96) {
        int r = 49 + tid / 32, c = tid & 31;
        qs[r][c] = 0.f; ks[r][c] = 0.f; vs[r][c] = 0.f;
    }
    __syncthreads();

    const float scale = 0.17677669529663687f;   // 32^-0.5

    if (tid < 169) {
        int ti = (tid / 13) * 4, tj = (tid % 13) * 4;
        float acc[4][4];
#pragma unroll
        for (int ii = 0; ii < 4; ii++)
#pragma unroll
            for (int jj = 0; jj < 4; jj++) acc[ii][jj] = 0.f;
#pragma unroll
        for (int c = 0; c < 32; c++) {
            float a[4], bb[4];
#pragma unroll
            for (int ii = 0; ii < 4; ii++) a[ii] = qs[ti + ii][c];
#pragma unroll
            for (int jj = 0; jj < 4; jj++) bb[jj] = ks[tj + jj][c];
#pragma unroll
            for (int ii = 0; ii < 4; ii++)
#pragma unroll
                for (int jj = 0; jj < 4; jj++) acc[ii][jj] += a[ii] * bb[jj];
        }
#pragma unroll
        for (int ii = 0; ii < 4; ii++)
#pragma unroll
            for (int jj = 0; jj < 4; jj++)
                S[(ti + ii) * 52 + tj + jj] = acc[ii][jj] * scale;
    }
    __syncthreads();

    if (tid < 49) {
        float m = -1e30f;
        for (int j = 0; j < 49; j++) m = fmaxf(m, S[tid * 52 + j]);
        float s = 0.f;
        for (int j = 0; j < 49; j++) {
            float e = __expf(S[tid * 52 + j] - m);
            S[tid * 52 + j] = e;
            s += e;
        }
        float inv = __fdividef(1.f, s);
        for (int j = 0; j < 49; j++) S[tid * 52 + j] *= inv;
    }
    __syncthreads();

    // ---- O = P @ v : 25 i-tiles (2 rows) x 8 d-tiles (4 ch) = 200 threads ----
    if (tid < 200) {
        int ti = (tid >> 3) * 2, td = (tid & 7) * 4;
        float acc[2][4];
#pragma unroll
        for (int ii = 0; ii < 2; ii++)
#pragma unroll
            for (int dd = 0; dd < 4; dd++) acc[ii][dd] = 0.f;
        for (int j = 0; j < 49; j++) {
            float p[2], v[4];
#pragma unroll
            for (int ii = 0; ii < 2; ii++) p[ii] = S[(ti + ii) * 52 + j];
#pragma unroll
            for (int dd = 0; dd < 4; dd++) v[dd] = vs[j][td + dd];
#pragma unroll
            for (int ii = 0; ii < 2; ii++)
#pragma unroll
                for (int dd = 0; dd < 4; dd++) acc[ii][dd] += p[ii] * v[dd];
        }
#pragma unroll
        for (int ii = 0; ii < 2; ii++) {
            int i = ti + ii;
            if (i < 49) {
                int n = (gy * 7 + i / 7) * 56 + gx * 7 + (i % 7);
                size_t ob = ((size_t)b * N_ + n) * 128 + h * 32 + td;
#pragma unroll
                for (int dd = 0; dd < 4; dd++) g_attn[ob + dd] = acc[ii][dd];
            }
        }
    }
}

// ============================================================================
// Tiled depthwise 3x3 conv on V + bias, float4 (R8, measured-good).
// ============================================================================
#define CONV_SMEM (10 * 58 * 32 * 4)   // 74240 B

__global__ __launch_bounds__(256) void conv_tiled(
    const float* __restrict__ w_lim, const float* __restrict__ b_lim)
{
    extern __shared__ float vsm[];     // [10 rows][58 x][32 ch]
    const int yt = blockIdx.x;         // 0..6
    const int c0 = blockIdx.y * 32;    // channel split
    const int b  = blockIdx.z;
    const int y0 = yt * 8;
    const int tid = threadIdx.x;

    for (int l = tid; l < 640; l += 256) {
        int r = l / 64;
        int side = (l >> 5) & 1;
        int c = l & 31;
        vsm[(r * 58 + (side ? 57 : 0)) * 32 + c] = 0.f;
    }
    for (int l = tid; l < 10 * 56 * 32; l += 256) {
        int c = l & 31;
        int x = (l >> 5) % 56;
        int r = (l >> 5) / 56;
        int Y = y0 + r - 1;
        float v = 0.f;
        if ((unsigned)Y < 56u)
            v = g_qkv[((size_t)b * N_ + Y * 56 + x) * 384 + 256 + c0 + c];
        vsm[(r * 58 + x + 1) * 32 + c] = v;
    }

    const int c4 = tid & 7;
    const int xq = tid >> 3;
    const int ch = c4 * 4;

    float4 w4[9];
#pragma unroll
    for (int t = 0; t < 9; t++) {
        w4[t].x = w_lim[(c0 + ch + 0) * 9 + t];
        w4[t].y = w_lim[(c0 + ch + 1) * 9 + t];
        w4[t].z = w_lim[(c0 + ch + 2) * 9 + t];
        w4[t].w = w_lim[(c0 + ch + 3) * 9 + t];
    }
    const float4 bias4 = *reinterpret_cast<const float4*>(b_lim + c0 + ch);

    __syncthreads();

    const float4* vsm4 = reinterpret_cast<const float4*>(vsm);

#pragma unroll
    for (int p = 0; p < 2; p++) {
        const int x = xq + 32 * p;
        if (x >= 56) break;
#pragma unroll
        for (int r = 0; r < 8; r++) {
            float4 acc = bias4;
#pragma unroll
            for (int dy = 0; dy < 3; dy++)
#pragma unroll
                for (int dx = 0; dx < 3; dx++) {
                    float4 v = vsm4[((r + dy) * 58 + x + dx) * 8 + c4];
                    float4 w = w4[dy * 3 + dx];
                    acc.x += w.x * v.x;
                    acc.y += w.y * v.y;
                    acc.z += w.z * v.z;
                    acc.w += w.w * v.w;
                }
            float4* ap = reinterpret_cast<float4*>(
                &g_attn[((size_t)b * N_ + (y0 + r) * 56 + x) * 128 + c0 + ch]);
            float4 o = *ap;
            o.x += acc.x; o.y += acc.y; o.z += acc.z; o.w += acc.w;
            *ap = o;
        }
    }
}

// ============================================================================
extern "C" void kernel_launch(void* const* d_in, const int* in_sizes, int n_in,
                              void* d_out, int out_size)
{
    const float* x      = (const float*)d_in[0];
    const float* w_qkv  = (const float*)d_in[1];
    const float* w_lim  = (const float*)d_in[2];
    const float* b_lim  = (const float*)d_in[3];
    const float* w_proj = (const float*)d_in[4];
    const float* b_proj = (const float*)d_in[5];
    float* out = (float*)d_out;

    float *qkv_ptr, *attn_ptr;
    __nv_bfloat16 *wh_ptr, *wl_ptr;
    cudaGetSymbolAddress((void**)&qkv_ptr,  g_qkv);
    cudaGetSymbolAddress((void**)&attn_ptr, g_attn);
    cudaGetSymbolAddress((void**)&wh_ptr,   g_wh);
    cudaGetSymbolAddress((void**)&wl_ptr,   g_wl);

    cudaFuncSetAttribute(hmma_gemm, cudaFuncAttributeMaxDynamicSharedMemorySize, SM_BYTES);
    cudaFuncSetAttribute(conv_tiled, cudaFuncAttributeMaxDynamicSharedMemorySize, CONV_SMEM);

    // 0) split weights into bf16 hi/lo
    prep_weights<<<(512 * 128 + 255) / 256, 256>>>(w_qkv, w_proj);

    // 1) qkv = x @ w_qkv^T  (A loaded+split once, 3 W tiles)
    hmma_gemm<<<M_TOT / 128, 256, SM_BYTES>>>(x, wh_ptr, wl_ptr, qkv_ptr, 384, 3, nullptr);

    // 2) windowed attention
    attn_kernel<<<B_ * 64 * NHEAD, 224>>>();

    // 3) tiled depthwise conv(v) + b_lim into g_attn (float4)
    conv_tiled<<<dim3(7, 4, B_), 256, CONV_SMEM>>>(w_lim, b_lim);

    // 4) out = g_attn @ w_proj^T + b_proj
    hmma_gemm<<<M_TOT / 128, 256, SM_BYTES>>>(attn_ptr, wh_ptr + 384 * 128,
                                              wl_ptr + 384 * 128, out, 128, 1, b_proj);
}

// round 14
// speedup vs baseline: 1.2492x; 1.0522x over previous
#include <cuda_runtime.h>
#include <cuda_bf16.h>
#include <cstdint>

#define B_    64
#define Himg  56
#define Wimg  56
#define C_    128
#define N_    3136
#define NHEAD 4
#define M_TOT (B_ * N_)     // 200704

// Scratch (allocation-free rule: device globals)
__device__ float g_qkv[(size_t)M_TOT * 384];           // 308 MB
__device__ float g_attn[(size_t)M_TOT * C_];           // 103 MB
__device__ __nv_bfloat16 g_wh[512 * 128];              // weights hi (qkv rows 0..383, proj 384..511)
__device__ __nv_bfloat16 g_wl[512 * 128];              // weights lo

// ============================================================================
// Weight split prep: fp32 -> bf16 hi/lo
// ============================================================================
__global__ void prep_weights(const float* __restrict__ w_qkv,
                             const float* __restrict__ w_proj)
{
    int idx = blockIdx.x * 256 + threadIdx.x;
    if (idx >= 512 * 128) return;
    float w = (idx < 384 * 128) ? w_qkv[idx] : w_proj[idx - 384 * 128];
    __nv_bfloat16 hi = __float2bfloat16(w);
    float r = w - __bfloat162float(hi);
    g_wh[idx] = hi;
    g_wl[idx] = __float2bfloat16(r);
}

// ============================================================================
// HMMA GEMM (R12, measured-best): tile 128x128, 256 threads (8 warps 4x2),
// warp tile 32x64, A-reuse ntiles loop, FUSED 3-stream k-loop.
// ============================================================================
#define LDT 136                      // padded row stride in bf16 elements
#define TILE_B (128 * LDT * 2)       // 34816 B per tile
#define SM_AHI 0
#define SM_ALO (TILE_B)
#define SM_WHI (2 * TILE_B)
#define SM_WLO (3 * TILE_B)
#define SM_BYTES (4 * TILE_B)

__device__ __forceinline__ uint32_t smem_u32(const void* p) {
    uint32_t a;
    asm("{ .reg .u64 t; cvta.to.shared.u64 t, %1; cvt.u32.u64 %0, t; }" : "=r"(a) : "l"(p));
    return a;
}

__device__ __forceinline__ uint32_t pack2(float a, float b) {
    __nv_bfloat16 ha = __float2bfloat16(a), hb = __float2bfloat16(b);
    unsigned short ua = reinterpret_cast<unsigned short&>(ha);
    unsigned short ub = reinterpret_cast<unsigned short&>(hb);
    return (uint32_t)ua | ((uint32_t)ub << 16);
}

__device__ __forceinline__ void mma16816(float* d, const uint32_t* a, const uint32_t* b) {
    asm volatile(
        "mma.sync.aligned.m16n8k16.row.col.f32.bf16.bf16.f32 "
        "{%0,%1,%2,%3}, {%4,%5,%6,%7}, {%8,%9}, {%0,%1,%2,%3};"
        : "+f"(d[0]), "+f"(d[1]), "+f"(d[2]), "+f"(d[3])
        : "r"(a[0]), "r"(a[1]), "r"(a[2]), "r"(a[3]), "r"(b[0]), "r"(b[1]));
}

__global__ void __launch_bounds__(256)
hmma_gemm(const float* __restrict__ A,
          const __nv_bfloat16* __restrict__ whi,
          const __nv_bfloat16* __restrict__ wlo,
          float* __restrict__ C, int ldc, int ntiles,
          const float* __restrict__ bias)
{
    extern __shared__ char smem[];
    const uint32_t sb = smem_u32(smem);
    const int tid = threadIdx.x;
    const int wid = tid >> 5;
    const int lane = tid & 31;
    const int m0 = blockIdx.x * 128;

    // ---- Load + split A tile (128 x 128 fp32 -> bf16 hi/lo), once ----
#pragma unroll
    for (int it = 0; it < 8; it++) {
        int e = it * 256 + tid;
        int r = e >> 4;
        int k0 = (e & 15) * 8;
        const float4* p = reinterpret_cast<const float4*>(A + (size_t)(m0 + r) * 128 + k0);
        float4 x0 = p[0], x1 = p[1];
        float f[8] = {x0.x, x0.y, x0.z, x0.w, x1.x, x1.y, x1.z, x1.w};
        uint32_t h[4], l[4];
#pragma unroll
        for (int j = 0; j < 4; j++) {
            float a = f[2 * j], b = f[2 * j + 1];
            __nv_bfloat16 ha = __float2bfloat16(a), hb = __float2bfloat16(b);
            float ra = a - __bfloat162float(ha);
            float rb = b - __bfloat162float(hb);
            unsigned short ua = reinterpret_cast<unsigned short&>(ha);
            unsigned short ub = reinterpret_cast<unsigned short&>(hb);
            h[j] = (uint32_t)ua | ((uint32_t)ub << 16);
            l[j] = pack2(ra, rb);
        }
        uint32_t off = (uint32_t)(r * LDT + k0) * 2;
        *reinterpret_cast<uint4*>(smem + SM_AHI + off) = make_uint4(h[0], h[1], h[2], h[3]);
        *reinterpret_cast<uint4*>(smem + SM_ALO + off) = make_uint4(l[0], l[1], l[2], l[3]);
    }

    const int mrow = (wid & 3) * 32;
    const int ncol = (wid >> 2) * 64;
    const int grp = lane >> 2;
    const int thr4 = lane & 3;

    for (int nt = 0; nt < ntiles; nt++) {
        const int n0 = nt * 128;
#pragma unroll
        for (int it = 0; it < 8; it++) {
            int e = it * 256 + tid;
            int r = e >> 4;
            int k0 = (e & 15) * 8;
            uint32_t off = (uint32_t)(r * LDT + k0) * 2;
            *reinterpret_cast<uint4*>(smem + SM_WHI + off) =
                *reinterpret_cast<const uint4*>(whi + (size_t)(n0 + r) * 128 + k0);
            *reinterpret_cast<uint4*>(smem + SM_WLO + off) =
                *reinterpret_cast<const uint4*>(wlo + (size_t)(n0 + r) * 128 + k0);
        }
        __syncthreads();

        float acc[2][8][4];
#pragma unroll
        for (int mt = 0; mt < 2; mt++)
#pragma unroll
            for (int ntt = 0; ntt < 8; ntt++)
#pragma unroll
                for (int j = 0; j < 4; j++) acc[mt][ntt][j] = 0.f;

#pragma unroll
        for (int ks = 0; ks < 8; ks++) {
            const int k0 = ks * 16;
            uint32_t ah[2][4], al[2][4];
#pragma unroll
            for (int mt = 0; mt < 2; mt++) {
                int r = mrow + mt * 16 + grp;
                uint32_t bh = sb + SM_AHI + (uint32_t)(r * LDT + k0 + thr4 * 2) * 2;
                uint32_t bl = sb + SM_ALO + (uint32_t)(r * LDT + k0 + thr4 * 2) * 2;
                asm volatile("ld.shared.b32 %0, [%1];" : "=r"(ah[mt][0]) : "r"(bh));
                asm volatile("ld.shared.b32 %0, [%1];" : "=r"(ah[mt][1]) : "r"(bh + 8 * LDT * 2));
                asm volatile("ld.shared.b32 %0, [%1];" : "=r"(ah[mt][2]) : "r"(bh + 16));
                asm volatile("ld.shared.b32 %0, [%1];" : "=r"(ah[mt][3]) : "r"(bh + 8 * LDT * 2 + 16));
                asm volatile("ld.shared.b32 %0, [%1];" : "=r"(al[mt][0]) : "r"(bl));
                asm volatile("ld.shared.b32 %0, [%1];" : "=r"(al[mt][1]) : "r"(bl + 8 * LDT * 2));
                asm volatile("ld.shared.b32 %0, [%1];" : "=r"(al[mt][2]) : "r"(bl + 16));
                asm volatile("ld.shared.b32 %0, [%1];" : "=r"(al[mt][3]) : "r"(bl + 8 * LDT * 2 + 16));
            }
#pragma unroll
            for (int ntt = 0; ntt < 8; ntt++) {
                int n = ncol + ntt * 8 + grp;
                uint32_t bh = sb + SM_WHI + (uint32_t)(n * LDT + k0 + thr4 * 2) * 2;
                uint32_t bl = sb + SM_WLO + (uint32_t)(n * LDT + k0 + thr4 * 2) * 2;
                uint32_t wh[2], wl2[2];
                asm volatile("ld.shared.b32 %0, [%1];" : "=r"(wh[0]) : "r"(bh));
                asm volatile("ld.shared.b32 %0, [%1];" : "=r"(wh[1]) : "r"(bh + 16));
                asm volatile("ld.shared.b32 %0, [%1];" : "=r"(wl2[0]) : "r"(bl));
                asm volatile("ld.shared.b32 %0, [%1];" : "=r"(wl2[1]) : "r"(bl + 16));
#pragma unroll
                for (int mt = 0; mt < 2; mt++) {
                    mma16816(acc[mt][ntt], ah[mt], wh);
                    mma16816(acc[mt][ntt], ah[mt], wl2);
                    mma16816(acc[mt][ntt], al[mt], wh);
                }
            }
        }

        // ---- Epilogue ----
#pragma unroll
        for (int mt = 0; mt < 2; mt++) {
            int r0 = m0 + mrow + mt * 16 + grp;
#pragma unroll
            for (int ntt = 0; ntt < 8; ntt++) {
                int c = n0 + ncol + ntt * 8 + thr4 * 2;
                float bx = 0.f, by = 0.f;
                if (bias) { bx = bias[c]; by = bias[c + 1]; }
                float2 v0 = make_float2(acc[mt][ntt][0] + bx, acc[mt][ntt][1] + by);
                float2 v1 = make_float2(acc[mt][ntt][2] + bx, acc[mt][ntt][3] + by);
                *reinterpret_cast<float2*>(C + (size_t)r0 * ldc + c) = v0;
                *reinterpret_cast<float2*>(C + (size_t)(r0 + 8) * ldc + c) = v1;
            }
        }
        __syncthreads();
    }
}

// ============================================================================
// Windowed attention, warp-autonomous: one block per (b, window, head),
// 224 threads = 7 warps; warp w owns query rows 7w..7w+6 end-to-end.
// Only one block-wide sync (after load). Softmax via shfl butterflies.
// vs is 16B-aligned (float4 loads!).
// ============================================================================
__global__ __launch_bounds__(224) void attn_kernel()
{
    const int idx = blockIdx.x;
    const int h = idx & 3;
    const int g = (idx >> 2) & 63;
    const int b = idx >> 8;
    const int gy = g >> 3, gx = g & 7;

    __shared__ __align__(16) float vs[49][36];   // stride 36: aligned float4 rows
    __shared__ __align__(16) float S[49 * 52];
    __shared__ float qs[49][33];
    __shared__ float ks[49][33];

    const int tid = threadIdx.x;

    for (int l = tid; l < 49 * 32; l += 224) {
        int i = l >> 5, c = l & 31;
        int n = (gy * 7 + i / 7) * 56 + gx * 7 + (i % 7);
        size_t base = ((size_t)b * N_ + n) * 384 + h * 32 + c;
        qs[i][c] = g_qkv[base];
        ks[i][c] = g_qkv[base + 128];
        vs[i][c] = g_qkv[base + 256];
    }
    __syncthreads();

    const float scale = 0.17677669529663687f;   // 32^-0.5
    const int warp = tid >> 5;
    const int lane = tid & 31;
    const int r0 = warp * 7;
    const bool v2 = (lane + 32) < 49;            // lane < 17

    // ---- S rows for this warp: thread owns cols {lane, lane+32} ----
    float s1[7], s2[7];
#pragma unroll
    for (int rr = 0; rr < 7; rr++) { s1[rr] = 0.f; s2[rr] = 0.f; }
#pragma unroll
    for (int c = 0; c < 32; c++) {
        float k1 = ks[lane][c];
        float k2 = v2 ? ks[lane + 32][c] : 0.f;
#pragma unroll
        for (int rr = 0; rr < 7; rr++) {
            float q = qs[r0 + rr][c];
            s1[rr] += q * k1;
            s2[rr] += q * k2;
        }
    }

    // ---- softmax per row (warp butterfly), P -> smem ----
#pragma unroll
    for (int rr = 0; rr < 7; rr++) {
        float a = s1[rr] * scale;
        float bb = v2 ? s2[rr] * scale : -1e30f;
        float m = fmaxf(a, bb);
#pragma unroll
        for (int o = 16; o >= 1; o >>= 1)
            m = fmaxf(m, __shfl_xor_sync(0xffffffffu, m, o));
        float e1 = __expf(a - m);
        float e2 = v2 ? __expf(bb - m) : 0.f;
        float sum = e1 + e2;
#pragma unroll
        for (int o = 16; o >= 1; o >>= 1)
            sum += __shfl_xor_sync(0xffffffffu, sum, o);
        float inv = __fdividef(1.f, sum);
        S[(r0 + rr) * 52 + lane] = e1 * inv;
        if (v2) S[(r0 + rr) * 52 + lane + 32] = e2 * inv;
    }
    __syncwarp();

    // ---- O rows: 4 lanes per row x 8 channels each (lanes 0..27) ----
    if (lane < 28) {
        const int rr = lane >> 2;
        const int d0 = (lane & 3) * 8;
        const int r = r0 + rr;
        float acc[8];
#pragma unroll
        for (int d = 0; d < 8; d++) acc[d] = 0.f;
        const float* Sr = S + r * 52;
        for (int j = 0; j < 49; j++) {
            float p = Sr[j];
            float4 va = *reinterpret_cast<const float4*>(&vs[j][d0]);
            float4 vb = *reinterpret_cast<const float4*>(&vs[j][d0 + 4]);
            acc[0] += p * va.x; acc[1] += p * va.y;
            acc[2] += p * va.z; acc[3] += p * va.w;
            acc[4] += p * vb.x; acc[5] += p * vb.y;
            acc[6] += p * vb.z; acc[7] += p * vb.w;
        }
        int n = (gy * 7 + r / 7) * 56 + gx * 7 + (r % 7);
        float* dst = &g_attn[((size_t)b * N_ + n) * 128 + h * 32 + d0];
        *reinterpret_cast<float4*>(dst) = make_float4(acc[0], acc[1], acc[2], acc[3]);
        *reinterpret_cast<float4*>(dst + 4) = make_float4(acc[4], acc[5], acc[6], acc[7]);
    }
}

// ============================================================================
// Tiled depthwise 3x3 conv on V + bias, float4; force 3 CTAs/SM.
// ============================================================================
#define CONV_SMEM (10 * 58 * 32 * 4)   // 74240 B

__global__ __launch_bounds__(256, 3) void conv_tiled(
    const float* __restrict__ w_lim, const float* __restrict__ b_lim)
{
    extern __shared__ float vsm[];     // [10 rows][58 x][32 ch]
    const int yt = blockIdx.x;         // 0..6
    const int c0 = blockIdx.y * 32;    // channel split
    const int b  = blockIdx.z;
    const int y0 = yt * 8;
    const int tid = threadIdx.x;

    for (int l = tid; l < 640; l += 256) {
        int r = l / 64;
        int side = (l >> 5) & 1;
        int c = l & 31;
        vsm[(r * 58 + (side ? 57 : 0)) * 32 + c] = 0.f;
    }
    for (int l = tid; l < 10 * 56 * 32; l += 256) {
        int c = l & 31;
        int x = (l >> 5) % 56;
        int r = (l >> 5) / 56;
        int Y = y0 + r - 1;
        float v = 0.f;
        if ((unsigned)Y < 56u)
            v = g_qkv[((size_t)b * N_ + Y * 56 + x) * 384 + 256 + c0 + c];
        vsm[(r * 58 + x + 1) * 32 + c] = v;
    }

    const int c4 = tid & 7;
    const int xq = tid >> 3;
    const int ch = c4 * 4;

    float4 w4[9];
#pragma unroll
    for (int t = 0; t < 9; t++) {
        w4[t].x = w_lim[(c0 + ch + 0) * 9 + t];
        w4[t].y = w_lim[(c0 + ch + 1) * 9 + t];
        w4[t].z = w_lim[(c0 + ch + 2) * 9 + t];
        w4[t].w = w_lim[(c0 + ch + 3) * 9 + t];
    }
    const float4 bias4 = *reinterpret_cast<const float4*>(b_lim + c0 + ch);

    __syncthreads();

    const float4* vsm4 = reinterpret_cast<const float4*>(vsm);

#pragma unroll
    for (int p = 0; p < 2; p++) {
        const int x = xq + 32 * p;
        if (x >= 56) break;
#pragma unroll
        for (int r = 0; r < 8; r++) {
            float4 acc = bias4;
#pragma unroll
            for (int dy = 0; dy < 3; dy++)
#pragma unroll
                for (int dx = 0; dx < 3; dx++) {
                    float4 v = vsm4[((r + dy) * 58 + x + dx) * 8 + c4];
                    float4 w = w4[dy * 3 + dx];
                    acc.x += w.x * v.x;
                    acc.y += w.y * v.y;
                    acc.z += w.z * v.z;
                    acc.w += w.w * v.w;
                }
            float4* ap = reinterpret_cast<float4*>(
                &g_attn[((size_t)b * N_ + (y0 + r) * 56 + x) * 128 + c0 + ch]);
            float4 o = *ap;
            o.x += acc.x; o.y += acc.y; o.z += acc.z; o.w += acc.w;
            *ap = o;
        }
    }
}

// ============================================================================
extern "C" void kernel_launch(void* const* d_in, const int* in_sizes, int n_in,
                              void* d_out, int out_size)
{
    const float* x      = (const float*)d_in[0];
    const float* w_qkv  = (const float*)d_in[1];
    const float* w_lim  = (const float*)d_in[2];
    const float* b_lim  = (const float*)d_in[3];
    const float* w_proj = (const float*)d_in[4];
    const float* b_proj = (const float*)d_in[5];
    float* out = (float*)d_out;

    float *qkv_ptr, *attn_ptr;
    __nv_bfloat16 *wh_ptr, *wl_ptr;
    cudaGetSymbolAddress((void**)&qkv_ptr,  g_qkv);
    cudaGetSymbolAddress((void**)&attn_ptr, g_attn);
    cudaGetSymbolAddress((void**)&wh_ptr,   g_wh);
    cudaGetSymbolAddress((void**)&wl_ptr,   g_wl);

    cudaFuncSetAttribute(hmma_gemm, cudaFuncAttributeMaxDynamicSharedMemorySize, SM_BYTES);
    cudaFuncSetAttribute(conv_tiled, cudaFuncAttributeMaxDynamicSharedMemorySize, CONV_SMEM);

    // 0) split weights into bf16 hi/lo
    prep_weights<<<(512 * 128 + 255) / 256, 256>>>(w_qkv, w_proj);

    // 1) qkv = x @ w_qkv^T  (A loaded+split once, 3 W tiles)
    hmma_gemm<<<M_TOT / 128, 256, SM_BYTES>>>(x, wh_ptr, wl_ptr, qkv_ptr, 384, 3, nullptr);

    // 2) windowed attention (warp-autonomous)
    attn_kernel<<<B_ * 64 * NHEAD, 224>>>();

    // 3) tiled depthwise conv(v) + b_lim into g_attn (float4, 3 CTAs/SM)
    conv_tiled<<<dim3(7, 4, B_), 256, CONV_SMEM>>>(w_lim, b_lim);

    // 4) out = g_attn @ w_proj^T + b_proj
    hmma_gemm<<<M_TOT / 128, 256, SM_BYTES>>>(attn_ptr, wh_ptr + 384 * 128,
                                              wl_ptr + 384 * 128, out, 128, 1, b_proj);
}

// round 15
// speedup vs baseline: 1.2565x; 1.0058x over previous
#include <cuda_runtime.h>
#include <cuda_bf16.h>
#include <cstdint>

#define B_    64
#define Himg  56
#define Wimg  56
#define C_    128
#define N_    3136
#define NHEAD 4
#define M_TOT (B_ * N_)     // 200704

// Scratch (allocation-free rule: device globals)
__device__ float g_qkv[(size_t)M_TOT * 384];           // 308 MB
__device__ float g_attn[(size_t)M_TOT * C_];           // 103 MB
__device__ __nv_bfloat16 g_wh[512 * 128];              // weights hi (qkv rows 0..383, proj 384..511)
__device__ __nv_bfloat16 g_wl[512 * 128];              // weights lo

// ============================================================================
// Weight split prep: fp32 -> bf16 hi/lo
// ============================================================================
__global__ void prep_weights(const float* __restrict__ w_qkv,
                             const float* __restrict__ w_proj)
{
    int idx = blockIdx.x * 256 + threadIdx.x;
    if (idx >= 512 * 128) return;
    float w = (idx < 384 * 128) ? w_qkv[idx] : w_proj[idx - 384 * 128];
    __nv_bfloat16 hi = __float2bfloat16(w);
    float r = w - __bfloat162float(hi);
    g_wh[idx] = hi;
    g_wl[idx] = __float2bfloat16(r);
}

// ============================================================================
// HMMA GEMM: R12 shape (128x128 CTA, 8 warps 4x2, warp 32x64, fused 3-stream
// k-loop, A-reuse ntiles loop) + ldmatrix.x4 fragment loads (12 per k-step
// instead of 48 scalar LDS). Mapping validated in R11.
// ============================================================================
#define LDT 136                      // padded row stride in bf16 elements
#define TILE_B (128 * LDT * 2)       // 34816 B per tile
#define SM_AHI 0
#define SM_ALO (TILE_B)
#define SM_WHI (2 * TILE_B)
#define SM_WLO (3 * TILE_B)
#define SM_BYTES (4 * TILE_B)

__device__ __forceinline__ uint32_t smem_u32(const void* p) {
    uint32_t a;
    asm("{ .reg .u64 t; cvta.to.shared.u64 t, %1; cvt.u32.u64 %0, t; }" : "=r"(a) : "l"(p));
    return a;
}

__device__ __forceinline__ uint32_t pack2(float a, float b) {
    __nv_bfloat16 ha = __float2bfloat16(a), hb = __float2bfloat16(b);
    unsigned short ua = reinterpret_cast<unsigned short&>(ha);
    unsigned short ub = reinterpret_cast<unsigned short&>(hb);
    return (uint32_t)ua | ((uint32_t)ub << 16);
}

__device__ __forceinline__ void mma16816(float* d, const uint32_t* a,
                                         uint32_t b0, uint32_t b1) {
    asm volatile(
        "mma.sync.aligned.m16n8k16.row.col.f32.bf16.bf16.f32 "
        "{%0,%1,%2,%3}, {%4,%5,%6,%7}, {%8,%9}, {%0,%1,%2,%3};"
        : "+f"(d[0]), "+f"(d[1]), "+f"(d[2]), "+f"(d[3])
        : "r"(a[0]), "r"(a[1]), "r"(a[2]), "r"(a[3]), "r"(b0), "r"(b1));
}

#define LDMX4(r, addr) \
    asm volatile("ldmatrix.sync.aligned.m8n8.x4.shared.b16 {%0,%1,%2,%3}, [%4];" \
        : "=r"((r)[0]), "=r"((r)[1]), "=r"((r)[2]), "=r"((r)[3]) : "r"(addr))

__global__ void __launch_bounds__(256)
hmma_gemm(const float* __restrict__ A,
          const __nv_bfloat16* __restrict__ whi,
          const __nv_bfloat16* __restrict__ wlo,
          float* __restrict__ C, int ldc, int ntiles,
          const float* __restrict__ bias)
{
    extern __shared__ char smem[];
    const uint32_t sb = smem_u32(smem);
    const int tid = threadIdx.x;
    const int wid = tid >> 5;
    const int lane = tid & 31;
    const int m0 = blockIdx.x * 128;

    // ---- Load + split A tile (128 x 128 fp32 -> bf16 hi/lo), once ----
#pragma unroll
    for (int it = 0; it < 8; it++) {
        int e = it * 256 + tid;
        int r = e >> 4;
        int k0 = (e & 15) * 8;
        const float4* p = reinterpret_cast<const float4*>(A + (size_t)(m0 + r) * 128 + k0);
        float4 x0 = p[0], x1 = p[1];
        float f[8] = {x0.x, x0.y, x0.z, x0.w, x1.x, x1.y, x1.z, x1.w};
        uint32_t h[4], l[4];
#pragma unroll
        for (int j = 0; j < 4; j++) {
            float a = f[2 * j], b = f[2 * j + 1];
            __nv_bfloat16 ha = __float2bfloat16(a), hb = __float2bfloat16(b);
            float ra = a - __bfloat162float(ha);
            float rb = b - __bfloat162float(hb);
            unsigned short ua = reinterpret_cast<unsigned short&>(ha);
            unsigned short ub = reinterpret_cast<unsigned short&>(hb);
            h[j] = (uint32_t)ua | ((uint32_t)ub << 16);
            l[j] = pack2(ra, rb);
        }
        uint32_t off = (uint32_t)(r * LDT + k0) * 2;
        *reinterpret_cast<uint4*>(smem + SM_AHI + off) = make_uint4(h[0], h[1], h[2], h[3]);
        *reinterpret_cast<uint4*>(smem + SM_ALO + off) = make_uint4(l[0], l[1], l[2], l[3]);
    }

    const int mrow = (wid & 3) * 32;
    const int ncol = (wid >> 2) * 64;
    const int grp = lane >> 2;
    const int thr4 = lane & 3;

    // ldmatrix lane addressing (R11-validated):
    // A tiles: t0 rows0-7@k0, t1 rows8-15@k0, t2 rows0-7@k8, t3 rows8-15@k8
    // B tiles: t0 n0-7@k0,   t1 n0-7@k8,   t2 n8-15@k0,  t3 n8-15@k8
    const int t = lane >> 3, lr = lane & 7;
    const uint32_t aoff =
        (uint32_t)(((mrow + (t & 1) * 8 + lr) * LDT) * 2 + (t >> 1) * 16);
    const uint32_t boff =
        (uint32_t)(((ncol + (t >> 1) * 8 + lr) * LDT) * 2 + (t & 1) * 16);

    for (int nt = 0; nt < ntiles; nt++) {
        const int n0 = nt * 128;
#pragma unroll
        for (int it = 0; it < 8; it++) {
            int e = it * 256 + tid;
            int r = e >> 4;
            int k0 = (e & 15) * 8;
            uint32_t off = (uint32_t)(r * LDT + k0) * 2;
            *reinterpret_cast<uint4*>(smem + SM_WHI + off) =
                *reinterpret_cast<const uint4*>(whi + (size_t)(n0 + r) * 128 + k0);
            *reinterpret_cast<uint4*>(smem + SM_WLO + off) =
                *reinterpret_cast<const uint4*>(wlo + (size_t)(n0 + r) * 128 + k0);
        }
        __syncthreads();

        float acc[2][8][4];
#pragma unroll
        for (int mt = 0; mt < 2; mt++)
#pragma unroll
            for (int ntt = 0; ntt < 8; ntt++)
#pragma unroll
                for (int j = 0; j < 4; j++) acc[mt][ntt][j] = 0.f;

        // ---- FUSED 3-stream k-loop with ldmatrix fragments ----
#pragma unroll
        for (int ks = 0; ks < 8; ks++) {
            const uint32_t kb = (uint32_t)(ks * 32);   // 16 bf16 = 32 B per k-step
            uint32_t ah[2][4], al[2][4];
#pragma unroll
            for (int mt = 0; mt < 2; mt++) {
                LDMX4(ah[mt], sb + SM_AHI + aoff + kb + (uint32_t)(mt * 16 * LDT * 2));
                LDMX4(al[mt], sb + SM_ALO + aoff + kb + (uint32_t)(mt * 16 * LDT * 2));
            }
            uint32_t wh[4][4], wl2[4][4];
#pragma unroll
            for (int p = 0; p < 4; p++) {
                LDMX4(wh[p],  sb + SM_WHI + boff + kb + (uint32_t)(p * 16 * LDT * 2));
                LDMX4(wl2[p], sb + SM_WLO + boff + kb + (uint32_t)(p * 16 * LDT * 2));
            }
#pragma unroll
            for (int ntt = 0; ntt < 8; ntt++) {
                const int p = ntt >> 1, s = (ntt & 1) * 2;
                const uint32_t bh0 = wh[p][s],  bh1 = wh[p][s + 1];
                const uint32_t bl0 = wl2[p][s], bl1 = wl2[p][s + 1];
#pragma unroll
                for (int mt = 0; mt < 2; mt++) {
                    mma16816(acc[mt][ntt], ah[mt], bh0, bh1);
                    mma16816(acc[mt][ntt], ah[mt], bl0, bl1);
                    mma16816(acc[mt][ntt], al[mt], bh0, bh1);
                }
            }
        }

        // ---- Epilogue ----
#pragma unroll
        for (int mt = 0; mt < 2; mt++) {
            int r0 = m0 + mrow + mt * 16 + grp;
#pragma unroll
            for (int ntt = 0; ntt < 8; ntt++) {
                int c = n0 + ncol + ntt * 8 + thr4 * 2;
                float bx = 0.f, by = 0.f;
                if (bias) { bx = bias[c]; by = bias[c + 1]; }
                float2 v0 = make_float2(acc[mt][ntt][0] + bx, acc[mt][ntt][1] + by);
                float2 v1 = make_float2(acc[mt][ntt][2] + bx, acc[mt][ntt][3] + by);
                *reinterpret_cast<float2*>(C + (size_t)r0 * ldc + c) = v0;
                *reinterpret_cast<float2*>(C + (size_t)(r0 + 8) * ldc + c) = v1;
            }
        }
        __syncthreads();
    }
}

// ============================================================================
// Windowed attention, warp-autonomous (R14, measured-good).
// ============================================================================
__global__ __launch_bounds__(224) void attn_kernel()
{
    const int idx = blockIdx.x;
    const int h = idx & 3;
    const int g = (idx >> 2) & 63;
    const int b = idx >> 8;
    const int gy = g >> 3, gx = g & 7;

    __shared__ __align__(16) float vs[49][36];
    __shared__ __align__(16) float S[49 * 52];
    __shared__ float qs[49][33];
    __shared__ float ks[49][33];

    const int tid = threadIdx.x;

    for (int l = tid; l < 49 * 32; l += 224) {
        int i = l >> 5, c = l & 31;
        int n = (gy * 7 + i / 7) * 56 + gx * 7 + (i % 7);
        size_t base = ((size_t)b * N_ + n) * 384 + h * 32 + c;
        qs[i][c] = g_qkv[base];
        ks[i][c] = g_qkv[base + 128];
        vs[i][c] = g_qkv[base + 256];
    }
    __syncthreads();

    const float scale = 0.17677669529663687f;   // 32^-0.5
    const int warp = tid >> 5;
    const int lane = tid & 31;
    const int r0 = warp * 7;
    const bool v2 = (lane + 32) < 49;

    float s1[7], s2[7];
#pragma unroll
    for (int rr = 0; rr < 7; rr++) { s1[rr] = 0.f; s2[rr] = 0.f; }
#pragma unroll
    for (int c = 0; c < 32; c++) {
        float k1 = ks[lane][c];
        float k2 = v2 ? ks[lane + 32][c] : 0.f;
#pragma unroll
        for (int rr = 0; rr < 7; rr++) {
            float q = qs[r0 + rr][c];
            s1[rr] += q * k1;
            s2[rr] += q * k2;
        }
    }

#pragma unroll
    for (int rr = 0; rr < 7; rr++) {
        float a = s1[rr] * scale;
        float bb = v2 ? s2[rr] * scale : -1e30f;
        float m = fmaxf(a, bb);
#pragma unroll
        for (int o = 16; o >= 1; o >>= 1)
            m = fmaxf(m, __shfl_xor_sync(0xffffffffu, m, o));
        float e1 = __expf(a - m);
        float e2 = v2 ? __expf(bb - m) : 0.f;
        float sum = e1 + e2;
#pragma unroll
        for (int o = 16; o >= 1; o >>= 1)
            sum += __shfl_xor_sync(0xffffffffu, sum, o);
        float inv = __fdividef(1.f, sum);
        S[(r0 + rr) * 52 + lane] = e1 * inv;
        if (v2) S[(r0 + rr) * 52 + lane + 32] = e2 * inv;
    }
    __syncwarp();

    if (lane < 28) {
        const int rr = lane >> 2;
        const int d0 = (lane & 3) * 8;
        const int r = r0 + rr;
        float acc[8];
#pragma unroll
        for (int d = 0; d < 8; d++) acc[d] = 0.f;
        const float* Sr = S + r * 52;
        for (int j = 0; j < 49; j++) {
            float p = Sr[j];
            float4 va = *reinterpret_cast<const float4*>(&vs[j][d0]);
            float4 vb = *reinterpret_cast<const float4*>(&vs[j][d0 + 4]);
            acc[0] += p * va.x; acc[1] += p * va.y;
            acc[2] += p * va.z; acc[3] += p * va.w;
            acc[4] += p * vb.x; acc[5] += p * vb.y;
            acc[6] += p * vb.z; acc[7] += p * vb.w;
        }
        int n = (gy * 7 + r / 7) * 56 + gx * 7 + (r % 7);
        float* dst = &g_attn[((size_t)b * N_ + n) * 128 + h * 32 + d0];
        *reinterpret_cast<float4*>(dst) = make_float4(acc[0], acc[1], acc[2], acc[3]);
        *reinterpret_cast<float4*>(dst + 4) = make_float4(acc[4], acc[5], acc[6], acc[7]);
    }
}

// ============================================================================
// Tiled depthwise 3x3 conv on V + bias, float4, 3 CTAs/SM (R14, measured-good).
// ============================================================================
#define CONV_SMEM (10 * 58 * 32 * 4)   // 74240 B

__global__ __launch_bounds__(256, 3) void conv_tiled(
    const float* __restrict__ w_lim, const float* __restrict__ b_lim)
{
    extern __shared__ float vsm[];     // [10 rows][58 x][32 ch]
    const int yt = blockIdx.x;
    const int c0 = blockIdx.y * 32;
    const int b  = blockIdx.z;
    const int y0 = yt * 8;
    const int tid = threadIdx.x;

    for (int l = tid; l < 640; l += 256) {
        int r = l / 64;
        int side = (l >> 5) & 1;
        int c = l & 31;
        vsm[(r * 58 + (side ? 57 : 0)) * 32 + c] = 0.f;
    }
    for (int l = tid; l < 10 * 56 * 32; l += 256) {
        int c = l & 31;
        int x = (l >> 5) % 56;
        int r = (l >> 5) / 56;
        int Y = y0 + r - 1;
        float v = 0.f;
        if ((unsigned)Y < 56u)
            v = g_qkv[((size_t)b * N_ + Y * 56 + x) * 384 + 256 + c0 + c];
        vsm[(r * 58 + x + 1) * 32 + c] = v;
    }

    const int c4 = tid & 7;
    const int xq = tid >> 3;
    const int ch = c4 * 4;

    float4 w4[9];
#pragma unroll
    for (int t = 0; t < 9; t++) {
        w4[t].x = w_lim[(c0 + ch + 0) * 9 + t];
        w4[t].y = w_lim[(c0 + ch + 1) * 9 + t];
        w4[t].z = w_lim[(c0 + ch + 2) * 9 + t];
        w4[t].w = w_lim[(c0 + ch + 3) * 9 + t];
    }
    const float4 bias4 = *reinterpret_cast<const float4*>(b_lim + c0 + ch);

    __syncthreads();

    const float4* vsm4 = reinterpret_cast<const float4*>(vsm);

#pragma unroll
    for (int p = 0; p < 2; p++) {
        const int x = xq + 32 * p;
        if (x >= 56) break;
#pragma unroll
        for (int r = 0; r < 8; r++) {
            float4 acc = bias4;
#pragma unroll
            for (int dy = 0; dy < 3; dy++)
#pragma unroll
                for (int dx = 0; dx < 3; dx++) {
                    float4 v = vsm4[((r + dy) * 58 + x + dx) * 8 + c4];
                    float4 w = w4[dy * 3 + dx];
                    acc.x += w.x * v.x;
                    acc.y += w.y * v.y;
                    acc.z += w.z * v.z;
                    acc.w += w.w * v.w;
                }
            float4* ap = reinterpret_cast<float4*>(
                &g_attn[((size_t)b * N_ + (y0 + r) * 56 + x) * 128 + c0 + ch]);
            float4 o = *ap;
            o.x += acc.x; o.y += acc.y; o.z += acc.z; o.w += acc.w;
            *ap = o;
        }
    }
}

// ============================================================================
extern "C" void kernel_launch(void* const* d_in, const int* in_sizes, int n_in,
                              void* d_out, int out_size)
{
    const float* x      = (const float*)d_in[0];
    const float* w_qkv  = (const float*)d_in[1];
    const float* w_lim  = (const float*)d_in[2];
    const float* b_lim  = (const float*)d_in[3];
    const float* w_proj = (const float*)d_in[4];
    const float* b_proj = (const float*)d_in[5];
    float* out = (float*)d_out;

    float *qkv_ptr, *attn_ptr;
    __nv_bfloat16 *wh_ptr, *wl_ptr;
    cudaGetSymbolAddress((void**)&qkv_ptr,  g_qkv);
    cudaGetSymbolAddress((void**)&attn_ptr, g_attn);
    cudaGetSymbolAddress((void**)&wh_ptr,   g_wh);
    cudaGetSymbolAddress((void**)&wl_ptr,   g_wl);

    cudaFuncSetAttribute(hmma_gemm, cudaFuncAttributeMaxDynamicSharedMemorySize, SM_BYTES);
    cudaFuncSetAttribute(conv_tiled, cudaFuncAttributeMaxDynamicSharedMemorySize, CONV_SMEM);

    // 0) split weights into bf16 hi/lo
    prep_weights<<<(512 * 128 + 255) / 256, 256>>>(w_qkv, w_proj);

    // 1) qkv = x @ w_qkv^T  (A loaded+split once, 3 W tiles)
    hmma_gemm<<<M_TOT / 128, 256, SM_BYTES>>>(x, wh_ptr, wl_ptr, qkv_ptr, 384, 3, nullptr);

    // 2) windowed attention (warp-autonomous)
    attn_kernel<<<B_ * 64 * NHEAD, 224>>>();

    // 3) tiled depthwise conv(v) + b_lim into g_attn (float4, 3 CTAs/SM)
    conv_tiled<<<dim3(7, 4, B_), 256, CONV_SMEM>>>(w_lim, b_lim);

    // 4) out = g_attn @ w_proj^T + b_proj
    hmma_gemm<<<M_TOT / 128, 256, SM_BYTES>>>(attn_ptr, wh_ptr + 384 * 128,
                                              wl_ptr + 384 * 128, out, 128, 1, b_proj);
}

// round 16
// speedup vs baseline: 1.2565x; 1.0000x over previous
#include <cuda_runtime.h>
#include <cuda_bf16.h>
#include <cstdint>

#define B_    64
#define Himg  56
#define Wimg  56
#define C_    128
#define N_    3136
#define NHEAD 4
#define M_TOT (B_ * N_)     // 200704

// Scratch (allocation-free rule: device globals)
__device__ float g_qkv[(size_t)M_TOT * 384];           // 308 MB
__device__ float g_attn[(size_t)M_TOT * C_];           // 103 MB
__device__ __nv_bfloat16 g_wh[512 * 128];              // weights hi (qkv rows 0..383, proj 384..511)
__device__ __nv_bfloat16 g_wl[512 * 128];              // weights lo

// ============================================================================
// Weight split prep: fp32 -> bf16 hi/lo
// ============================================================================
__global__ void prep_weights(const float* __restrict__ w_qkv,
                             const float* __restrict__ w_proj)
{
    int idx = blockIdx.x * 256 + threadIdx.x;
    if (idx >= 512 * 128) return;
    float w = (idx < 384 * 128) ? w_qkv[idx] : w_proj[idx - 384 * 128];
    __nv_bfloat16 hi = __float2bfloat16(w);
    float r = w - __bfloat162float(hi);
    g_wh[idx] = hi;
    g_wl[idx] = __float2bfloat16(r);
}

// ============================================================================
// HMMA GEMM: R15 core (128x128 CTA, 8 warps 4x2, warp 32x64, fused 3-stream
// k-loop, ldmatrix fragments) + cp.async DOUBLE-BUFFERED W tiles: W(nt+1) DMA
// overlaps MMA of W(nt); W(0) overlaps the A split.
// ============================================================================
#define LDT 136                      // padded row stride in bf16 elements
#define TILE_B (128 * LDT * 2)       // 34816 B per (hi or lo) tile
#define SM_AHI 0
#define SM_ALO (TILE_B)
#define SM_W0  (2 * TILE_B)          // W buffer 0: hi at +0, lo at +TILE_B
#define SM_W1  (4 * TILE_B)          // W buffer 1
#define SM_BYTES (6 * TILE_B)        // 208896 B (<= 227KB cap), 1 CTA/SM

__device__ __forceinline__ uint32_t smem_u32(const void* p) {
    uint32_t a;
    asm("{ .reg .u64 t; cvta.to.shared.u64 t, %1; cvt.u32.u64 %0, t; }" : "=r"(a) : "l"(p));
    return a;
}

__device__ __forceinline__ uint32_t pack2(float a, float b) {
    __nv_bfloat16 ha = __float2bfloat16(a), hb = __float2bfloat16(b);
    unsigned short ua = reinterpret_cast<unsigned short&>(ha);
    unsigned short ub = reinterpret_cast<unsigned short&>(hb);
    return (uint32_t)ua | ((uint32_t)ub << 16);
}

__device__ __forceinline__ void mma16816(float* d, const uint32_t* a,
                                         uint32_t b0, uint32_t b1) {
    asm volatile(
        "mma.sync.aligned.m16n8k16.row.col.f32.bf16.bf16.f32 "
        "{%0,%1,%2,%3}, {%4,%5,%6,%7}, {%8,%9}, {%0,%1,%2,%3};"
        : "+f"(d[0]), "+f"(d[1]), "+f"(d[2]), "+f"(d[3])
        : "r"(a[0]), "r"(a[1]), "r"(a[2]), "r"(a[3]), "r"(b0), "r"(b1));
}

#define LDMX4(r, addr) \
    asm volatile("ldmatrix.sync.aligned.m8n8.x4.shared.b16 {%0,%1,%2,%3}, [%4];" \
        : "=r"((r)[0]), "=r"((r)[1]), "=r"((r)[2]), "=r"((r)[3]) : "r"(addr))

#define CP16(dst, src) \
    asm volatile("cp.async.cg.shared.global [%0], [%1], 16;" :: "r"(dst), "l"(src))
#define CP_COMMIT() asm volatile("cp.async.commit_group;" ::: "memory")
#define CP_WAIT0()  asm volatile("cp.async.wait_group 0;" ::: "memory")
#define CP_WAIT1()  asm volatile("cp.async.wait_group 1;" ::: "memory")

__global__ void __launch_bounds__(256)
hmma_gemm(const float* __restrict__ A,
          const __nv_bfloat16* __restrict__ whi,
          const __nv_bfloat16* __restrict__ wlo,
          float* __restrict__ C, int ldc, int ntiles,
          const float* __restrict__ bias)
{
    extern __shared__ char smem[];
    const uint32_t sb = smem_u32(smem);
    const int tid = threadIdx.x;
    const int wid = tid >> 5;
    const int lane = tid & 31;
    const int m0 = blockIdx.x * 128;

    // W-tile async copy: 8 chunks x (hi, lo) per thread
    auto issue_W = [&](int nt, uint32_t wbuf) {
#pragma unroll
        for (int it = 0; it < 8; it++) {
            int e = it * 256 + tid;
            int r = e >> 4;
            int k0 = (e & 15) * 8;
            uint32_t off = (uint32_t)(r * LDT + k0) * 2;
            const size_t gof = (size_t)(nt * 128 + r) * 128 + k0;
            CP16(wbuf + off, whi + gof);
            CP16(wbuf + TILE_B + off, wlo + gof);
        }
    };

    // ---- Prologue: start W(0) DMA, then split A (overlapped) ----
    issue_W(0, sb + SM_W0);
    CP_COMMIT();

#pragma unroll
    for (int it = 0; it < 8; it++) {
        int e = it * 256 + tid;
        int r = e >> 4;
        int k0 = (e & 15) * 8;
        const float4* p = reinterpret_cast<const float4*>(A + (size_t)(m0 + r) * 128 + k0);
        float4 x0 = p[0], x1 = p[1];
        float f[8] = {x0.x, x0.y, x0.z, x0.w, x1.x, x1.y, x1.z, x1.w};
        uint32_t h[4], l[4];
#pragma unroll
        for (int j = 0; j < 4; j++) {
            float a = f[2 * j], b = f[2 * j + 1];
            __nv_bfloat16 ha = __float2bfloat16(a), hb = __float2bfloat16(b);
            float ra = a - __bfloat162float(ha);
            float rb = b - __bfloat162float(hb);
            unsigned short ua = reinterpret_cast<unsigned short&>(ha);
            unsigned short ub = reinterpret_cast<unsigned short&>(hb);
            h[j] = (uint32_t)ua | ((uint32_t)ub << 16);
            l[j] = pack2(ra, rb);
        }
        uint32_t off = (uint32_t)(r * LDT + k0) * 2;
        *reinterpret_cast<uint4*>(smem + SM_AHI + off) = make_uint4(h[0], h[1], h[2], h[3]);
        *reinterpret_cast<uint4*>(smem + SM_ALO + off) = make_uint4(l[0], l[1], l[2], l[3]);
    }

    const int mrow = (wid & 3) * 32;
    const int ncol = (wid >> 2) * 64;
    const int grp = lane >> 2;
    const int thr4 = lane & 3;

    // ldmatrix lane addressing (validated):
    const int t = lane >> 3, lr = lane & 7;
    const uint32_t aoff =
        (uint32_t)(((mrow + (t & 1) * 8 + lr) * LDT) * 2 + (t >> 1) * 16);
    const uint32_t boff =
        (uint32_t)(((ncol + (t >> 1) * 8 + lr) * LDT) * 2 + (t & 1) * 16);

    for (int nt = 0; nt < ntiles; nt++) {
        const int n0 = nt * 128;
        const uint32_t wcur = sb + ((nt & 1) ? SM_W1 : SM_W0);

        // start next W DMA (into the other buffer), then wait for current
        if (nt + 1 < ntiles) {
            issue_W(nt + 1, sb + (((nt + 1) & 1) ? SM_W1 : SM_W0));
            CP_COMMIT();
            CP_WAIT1();            // all groups except the newest are done
        } else {
            CP_WAIT0();
        }
        __syncthreads();           // W(nt) visible to all; prev buffer free

        float acc[2][8][4];
#pragma unroll
        for (int mt = 0; mt < 2; mt++)
#pragma unroll
            for (int ntt = 0; ntt < 8; ntt++)
#pragma unroll
                for (int j = 0; j < 4; j++) acc[mt][ntt][j] = 0.f;

        // ---- FUSED 3-stream k-loop with ldmatrix fragments ----
#pragma unroll
        for (int ks = 0; ks < 8; ks++) {
            const uint32_t kb = (uint32_t)(ks * 32);
            uint32_t ah[2][4], al[2][4];
#pragma unroll
            for (int mt = 0; mt < 2; mt++) {
                LDMX4(ah[mt], sb + SM_AHI + aoff + kb + (uint32_t)(mt * 16 * LDT * 2));
                LDMX4(al[mt], sb + SM_ALO + aoff + kb + (uint32_t)(mt * 16 * LDT * 2));
            }
            uint32_t wh[4][4], wl2[4][4];
#pragma unroll
            for (int p = 0; p < 4; p++) {
                LDMX4(wh[p],  wcur + boff + kb + (uint32_t)(p * 16 * LDT * 2));
                LDMX4(wl2[p], wcur + TILE_B + boff + kb + (uint32_t)(p * 16 * LDT * 2));
            }
#pragma unroll
            for (int ntt = 0; ntt < 8; ntt++) {
                const int p = ntt >> 1, s = (ntt & 1) * 2;
                const uint32_t bh0 = wh[p][s],  bh1 = wh[p][s + 1];
                const uint32_t bl0 = wl2[p][s], bl1 = wl2[p][s + 1];
#pragma unroll
                for (int mt = 0; mt < 2; mt++) {
                    mma16816(acc[mt][ntt], ah[mt], bh0, bh1);
                    mma16816(acc[mt][ntt], ah[mt], bl0, bl1);
                    mma16816(acc[mt][ntt], al[mt], bh0, bh1);
                }
            }
        }

        // ---- Epilogue ----
#pragma unroll
        for (int mt = 0; mt < 2; mt++) {
            int r0 = m0 + mrow + mt * 16 + grp;
#pragma unroll
            for (int ntt = 0; ntt < 8; ntt++) {
                int c = n0 + ncol + ntt * 8 + thr4 * 2;
                float bx = 0.f, by = 0.f;
                if (bias) { bx = bias[c]; by = bias[c + 1]; }
                float2 v0 = make_float2(acc[mt][ntt][0] + bx, acc[mt][ntt][1] + by);
                float2 v1 = make_float2(acc[mt][ntt][2] + bx, acc[mt][ntt][3] + by);
                *reinterpret_cast<float2*>(C + (size_t)r0 * ldc + c) = v0;
                *reinterpret_cast<float2*>(C + (size_t)(r0 + 8) * ldc + c) = v1;
            }
        }
        __syncthreads();           // protect buffer reuse next iteration
    }
}

// ============================================================================
// Windowed attention, warp-autonomous (R14, measured-good).
// ============================================================================
__global__ __launch_bounds__(224) void attn_kernel()
{
    const int idx = blockIdx.x;
    const int h = idx & 3;
    const int g = (idx >> 2) & 63;
    const int b = idx >> 8;
    const int gy = g >> 3, gx = g & 7;

    __shared__ __align__(16) float vs[49][36];
    __shared__ __align__(16) float S[49 * 52];
    __shared__ float qs[49][33];
    __shared__ float ks[49][33];

    const int tid = threadIdx.x;

    for (int l = tid; l < 49 * 32; l += 224) {
        int i = l >> 5, c = l & 31;
        int n = (gy * 7 + i / 7) * 56 + gx * 7 + (i % 7);
        size_t base = ((size_t)b * N_ + n) * 384 + h * 32 + c;
        qs[i][c] = g_qkv[base];
        ks[i][c] = g_qkv[base + 128];
        vs[i][c] = g_qkv[base + 256];
    }
    __syncthreads();

    const float scale = 0.17677669529663687f;   // 32^-0.5
    const int warp = tid >> 5;
    const int lane = tid & 31;
    const int r0 = warp * 7;
    const bool v2 = (lane + 32) < 49;

    float s1[7], s2[7];
#pragma unroll
    for (int rr = 0; rr < 7; rr++) { s1[rr] = 0.f; s2[rr] = 0.f; }
#pragma unroll
    for (int c = 0; c < 32; c++) {
        float k1 = ks[lane][c];
        float k2 = v2 ? ks[lane + 32][c] : 0.f;
#pragma unroll
        for (int rr = 0; rr < 7; rr++) {
            float q = qs[r0 + rr][c];
            s1[rr] += q * k1;
            s2[rr] += q * k2;
        }
    }

#pragma unroll
    for (int rr = 0; rr < 7; rr++) {
        float a = s1[rr] * scale;
        float bb = v2 ? s2[rr] * scale : -1e30f;
        float m = fmaxf(a, bb);
#pragma unroll
        for (int o = 16; o >= 1; o >>= 1)
            m = fmaxf(m, __shfl_xor_sync(0xffffffffu, m, o));
        float e1 = __expf(a - m);
        float e2 = v2 ? __expf(bb - m) : 0.f;
        float sum = e1 + e2;
#pragma unroll
        for (int o = 16; o >= 1; o >>= 1)
            sum += __shfl_xor_sync(0xffffffffu, sum, o);
        float inv = __fdividef(1.f, sum);
        S[(r0 + rr) * 52 + lane] = e1 * inv;
        if (v2) S[(r0 + rr) * 52 + lane + 32] = e2 * inv;
    }
    __syncwarp();

    if (lane < 28) {
        const int rr = lane >> 2;
        const int d0 = (lane & 3) * 8;
        const int r = r0 + rr;
        float acc[8];
#pragma unroll
        for (int d = 0; d < 8; d++) acc[d] = 0.f;
        const float* Sr = S + r * 52;
        for (int j = 0; j < 49; j++) {
            float p = Sr[j];
            float4 va = *reinterpret_cast<const float4*>(&vs[j][d0]);
            float4 vb = *reinterpret_cast<const float4*>(&vs[j][d0 + 4]);
            acc[0] += p * va.x; acc[1] += p * va.y;
            acc[2] += p * va.z; acc[3] += p * va.w;
            acc[4] += p * vb.x; acc[5] += p * vb.y;
            acc[6] += p * vb.z; acc[7] += p * vb.w;
        }
        int n = (gy * 7 + r / 7) * 56 + gx * 7 + (r % 7);
        float* dst = &g_attn[((size_t)b * N_ + n) * 128 + h * 32 + d0];
        *reinterpret_cast<float4*>(dst) = make_float4(acc[0], acc[1], acc[2], acc[3]);
        *reinterpret_cast<float4*>(dst + 4) = make_float4(acc[4], acc[5], acc[6], acc[7]);
    }
}

// ============================================================================
// Tiled depthwise 3x3 conv on V + bias, float4, 3 CTAs/SM (R14, measured-good).
// ============================================================================
#define CONV_SMEM (10 * 58 * 32 * 4)   // 74240 B

__global__ __launch_bounds__(256, 3) void conv_tiled(
    const float* __restrict__ w_lim, const float* __restrict__ b_lim)
{
    extern __shared__ float vsm[];     // [10 rows][58 x][32 ch]
    const int yt = blockIdx.x;
    const int c0 = blockIdx.y * 32;
    const int b  = blockIdx.z;
    const int y0 = yt * 8;
    const int tid = threadIdx.x;

    for (int l = tid; l < 640; l += 256) {
        int r = l / 64;
        int side = (l >> 5) & 1;
        int c = l & 31;
        vsm[(r * 58 + (side ? 57 : 0)) * 32 + c] = 0.f;
    }
    for (int l = tid; l < 10 * 56 * 32; l += 256) {
        int c = l & 31;
        int x = (l >> 5) % 56;
        int r = (l >> 5) / 56;
        int Y = y0 + r - 1;
        float v = 0.f;
        if ((unsigned)Y < 56u)
            v = g_qkv[((size_t)b * N_ + Y * 56 + x) * 384 + 256 + c0 + c];
        vsm[(r * 58 + x + 1) * 32 + c] = v;
    }

    const int c4 = tid & 7;
    const int xq = tid >> 3;
    const int ch = c4 * 4;

    float4 w4[9];
#pragma unroll
    for (int t = 0; t < 9; t++) {
        w4[t].x = w_lim[(c0 + ch + 0) * 9 + t];
        w4[t].y = w_lim[(c0 + ch + 1) * 9 + t];
        w4[t].z = w_lim[(c0 + ch + 2) * 9 + t];
        w4[t].w = w_lim[(c0 + ch + 3) * 9 + t];
    }
    const float4 bias4 = *reinterpret_cast<const float4*>(b_lim + c0 + ch);

    __syncthreads();

    const float4* vsm4 = reinterpret_cast<const float4*>(vsm);

#pragma unroll
    for (int p = 0; p < 2; p++) {
        const int x = xq + 32 * p;
        if (x >= 56) break;
#pragma unroll
        for (int r = 0; r < 8; r++) {
            float4 acc = bias4;
#pragma unroll
            for (int dy = 0; dy < 3; dy++)
#pragma unroll
                for (int dx = 0; dx < 3; dx++) {
                    float4 v = vsm4[((r + dy) * 58 + x + dx) * 8 + c4];
                    float4 w = w4[dy * 3 + dx];
                    acc.x += w.x * v.x;
                    acc.y += w.y * v.y;
                    acc.z += w.z * v.z;
                    acc.w += w.w * v.w;
                }
            float4* ap = reinterpret_cast<float4*>(
                &g_attn[((size_t)b * N_ + (y0 + r) * 56 + x) * 128 + c0 + ch]);
            float4 o = *ap;
            o.x += acc.x; o.y += acc.y; o.z += acc.z; o.w += acc.w;
            *ap = o;
        }
    }
}

// ============================================================================
extern "C" void kernel_launch(void* const* d_in, const int* in_sizes, int n_in,
                              void* d_out, int out_size)
{
    const float* x      = (const float*)d_in[0];
    const float* w_qkv  = (const float*)d_in[1];
    const float* w_lim  = (const float*)d_in[2];
    const float* b_lim  = (const float*)d_in[3];
    const float* w_proj = (const float*)d_in[4];
    const float* b_proj = (const float*)d_in[5];
    float* out = (float*)d_out;

    float *qkv_ptr, *attn_ptr;
    __nv_bfloat16 *wh_ptr, *wl_ptr;
    cudaGetSymbolAddress((void**)&qkv_ptr,  g_qkv);
    cudaGetSymbolAddress((void**)&attn_ptr, g_attn);
    cudaGetSymbolAddress((void**)&wh_ptr,   g_wh);
    cudaGetSymbolAddress((void**)&wl_ptr,   g_wl);

    cudaFuncSetAttribute(hmma_gemm, cudaFuncAttributeMaxDynamicSharedMemorySize, SM_BYTES);
    cudaFuncSetAttribute(conv_tiled, cudaFuncAttributeMaxDynamicSharedMemorySize, CONV_SMEM);

    // 0) split weights into bf16 hi/lo
    prep_weights<<<(512 * 128 + 255) / 256, 256>>>(w_qkv, w_proj);

    // 1) qkv = x @ w_qkv^T  (A split overlapped with W0 DMA; W double-buffered)
    hmma_gemm<<<M_TOT / 128, 256, SM_BYTES>>>(x, wh_ptr, wl_ptr, qkv_ptr, 384, 3, nullptr);

    // 2) windowed attention (warp-autonomous)
    attn_kernel<<<B_ * 64 * NHEAD, 224>>>();

    // 3) tiled depthwise conv(v) + b_lim into g_attn (float4, 3 CTAs/SM)
    conv_tiled<<<dim3(7, 4, B_), 256, CONV_SMEM>>>(w_lim, b_lim);

    // 4) out = g_attn @ w_proj^T + b_proj
    hmma_gemm<<<M_TOT / 128, 256, SM_BYTES>>>(attn_ptr, wh_ptr + 384 * 128,
                                              wl_ptr + 384 * 128, out, 128, 1, b_proj);
}

// round 17
// speedup vs baseline: 1.3153x; 1.0468x over previous
#include <cuda_runtime.h>
#include <cuda_bf16.h>
#include <cstdint>

#define B_    64
#define Himg  56
#define Wimg  56
#define C_    128
#define N_    3136
#define NHEAD 4
#define M_TOT (B_ * N_)     // 200704

// Scratch (allocation-free rule: device globals)
__device__ float g_qkv[(size_t)M_TOT * 384];           // 308 MB
__device__ float g_attn[(size_t)M_TOT * C_];           // 103 MB
__device__ __nv_bfloat16 g_wh[512 * 128];              // weights hi (qkv rows 0..383, proj 384..511)
__device__ __nv_bfloat16 g_wl[512 * 128];              // weights lo

// ============================================================================
// Weight split prep: fp32 -> bf16 hi/lo
// ============================================================================
__global__ void prep_weights(const float* __restrict__ w_qkv,
                             const float* __restrict__ w_proj)
{
    int idx = blockIdx.x * 256 + threadIdx.x;
    if (idx >= 512 * 128) return;
    float w = (idx < 384 * 128) ? w_qkv[idx] : w_proj[idx - 384 * 128];
    __nv_bfloat16 hi = __float2bfloat16(w);
    float r = w - __bfloat162float(hi);
    g_wh[idx] = hi;
    g_wl[idx] = __float2bfloat16(r);
}

// ============================================================================
// HMMA GEMM: fused 3-stream k-loop + ldmatrix (validated), BN=64 W tiles
// -> smem 102 KB -> 2 CTAs/SM. 8 warps: 4 along M x 2 along N, warp 32x32.
// A (128x128) split once; ntiles x 64-col W tiles.
// ============================================================================
#define LDT 136                      // padded row stride in bf16 elements
#define TILE_A (128 * LDT * 2)       // 34816 B per A (hi or lo) tile
#define TILE_W (64 * LDT * 2)        // 17408 B per W (hi or lo) tile
#define SM_AHI 0
#define SM_ALO (TILE_A)
#define SM_WHI (2 * TILE_A)
#define SM_WLO (2 * TILE_A + TILE_W)
#define SM_BYTES (2 * TILE_A + 2 * TILE_W)   // 104448 B -> 2 CTAs/SM

__device__ __forceinline__ uint32_t smem_u32(const void* p) {
    uint32_t a;
    asm("{ .reg .u64 t; cvta.to.shared.u64 t, %1; cvt.u32.u64 %0, t; }" : "=r"(a) : "l"(p));
    return a;
}

__device__ __forceinline__ uint32_t pack2(float a, float b) {
    __nv_bfloat16 ha = __float2bfloat16(a), hb = __float2bfloat16(b);
    unsigned short ua = reinterpret_cast<unsigned short&>(ha);
    unsigned short ub = reinterpret_cast<unsigned short&>(hb);
    return (uint32_t)ua | ((uint32_t)ub << 16);
}

__device__ __forceinline__ void mma16816(float* d, const uint32_t* a,
                                         uint32_t b0, uint32_t b1) {
    asm volatile(
        "mma.sync.aligned.m16n8k16.row.col.f32.bf16.bf16.f32 "
        "{%0,%1,%2,%3}, {%4,%5,%6,%7}, {%8,%9}, {%0,%1,%2,%3};"
        : "+f"(d[0]), "+f"(d[1]), "+f"(d[2]), "+f"(d[3])
        : "r"(a[0]), "r"(a[1]), "r"(a[2]), "r"(a[3]), "r"(b0), "r"(b1));
}

#define LDMX4(r, addr) \
    asm volatile("ldmatrix.sync.aligned.m8n8.x4.shared.b16 {%0,%1,%2,%3}, [%4];" \
        : "=r"((r)[0]), "=r"((r)[1]), "=r"((r)[2]), "=r"((r)[3]) : "r"(addr))

__global__ void __launch_bounds__(256, 2)
hmma_gemm(const float* __restrict__ A,
          const __nv_bfloat16* __restrict__ whi,
          const __nv_bfloat16* __restrict__ wlo,
          float* __restrict__ C, int ldc, int ntiles,
          const float* __restrict__ bias)
{
    extern __shared__ char smem[];
    const uint32_t sb = smem_u32(smem);
    const int tid = threadIdx.x;
    const int wid = tid >> 5;
    const int lane = tid & 31;
    const int m0 = blockIdx.x * 128;

    // ---- Load + split A tile (128 x 128 fp32 -> bf16 hi/lo), once ----
#pragma unroll
    for (int it = 0; it < 8; it++) {
        int e = it * 256 + tid;
        int r = e >> 4;
        int k0 = (e & 15) * 8;
        const float4* p = reinterpret_cast<const float4*>(A + (size_t)(m0 + r) * 128 + k0);
        float4 x0 = p[0], x1 = p[1];
        float f[8] = {x0.x, x0.y, x0.z, x0.w, x1.x, x1.y, x1.z, x1.w};
        uint32_t h[4], l[4];
#pragma unroll
        for (int j = 0; j < 4; j++) {
            float a = f[2 * j], b = f[2 * j + 1];
            __nv_bfloat16 ha = __float2bfloat16(a), hb = __float2bfloat16(b);
            float ra = a - __bfloat162float(ha);
            float rb = b - __bfloat162float(hb);
            unsigned short ua = reinterpret_cast<unsigned short&>(ha);
            unsigned short ub = reinterpret_cast<unsigned short&>(hb);
            h[j] = (uint32_t)ua | ((uint32_t)ub << 16);
            l[j] = pack2(ra, rb);
        }
        uint32_t off = (uint32_t)(r * LDT + k0) * 2;
        *reinterpret_cast<uint4*>(smem + SM_AHI + off) = make_uint4(h[0], h[1], h[2], h[3]);
        *reinterpret_cast<uint4*>(smem + SM_ALO + off) = make_uint4(l[0], l[1], l[2], l[3]);
    }

    const int mrow = (wid & 3) * 32;      // 4 warps along M
    const int ncol = (wid >> 2) * 32;     // 2 warps along N (BN=64)
    const int grp = lane >> 2;
    const int thr4 = lane & 3;

    // ldmatrix lane addressing (validated):
    const int t = lane >> 3, lr = lane & 7;
    const uint32_t aoff =
        (uint32_t)(((mrow + (t & 1) * 8 + lr) * LDT) * 2 + (t >> 1) * 16);
    const uint32_t boff =
        (uint32_t)(((ncol + (t >> 1) * 8 + lr) * LDT) * 2 + (t & 1) * 16);

    for (int nt = 0; nt < ntiles; nt++) {
        const int n0 = nt * 64;
        // ---- Load W tiles for this 64-col block ----
#pragma unroll
        for (int it = 0; it < 4; it++) {
            int e = it * 256 + tid;
            int r = e >> 4;            // 0..63
            int k0 = (e & 15) * 8;
            uint32_t off = (uint32_t)(r * LDT + k0) * 2;
            *reinterpret_cast<uint4*>(smem + SM_WHI + off) =
                *reinterpret_cast<const uint4*>(whi + (size_t)(n0 + r) * 128 + k0);
            *reinterpret_cast<uint4*>(smem + SM_WLO + off) =
                *reinterpret_cast<const uint4*>(wlo + (size_t)(n0 + r) * 128 + k0);
        }
        __syncthreads();

        float acc[2][4][4];
#pragma unroll
        for (int mt = 0; mt < 2; mt++)
#pragma unroll
            for (int ntt = 0; ntt < 4; ntt++)
#pragma unroll
                for (int j = 0; j < 4; j++) acc[mt][ntt][j] = 0.f;

        // ---- FUSED 3-stream k-loop with ldmatrix fragments ----
#pragma unroll
        for (int ks = 0; ks < 8; ks++) {
            const uint32_t kb = (uint32_t)(ks * 32);
            uint32_t ah[2][4], al[2][4];
#pragma unroll
            for (int mt = 0; mt < 2; mt++) {
                LDMX4(ah[mt], sb + SM_AHI + aoff + kb + (uint32_t)(mt * 16 * LDT * 2));
                LDMX4(al[mt], sb + SM_ALO + aoff + kb + (uint32_t)(mt * 16 * LDT * 2));
            }
            uint32_t wh[2][4], wl2[2][4];
#pragma unroll
            for (int p = 0; p < 2; p++) {
                LDMX4(wh[p],  sb + SM_WHI + boff + kb + (uint32_t)(p * 16 * LDT * 2));
                LDMX4(wl2[p], sb + SM_WLO + boff + kb + (uint32_t)(p * 16 * LDT * 2));
            }
#pragma unroll
            for (int ntt = 0; ntt < 4; ntt++) {
                const int p = ntt >> 1, s = (ntt & 1) * 2;
                const uint32_t bh0 = wh[p][s],  bh1 = wh[p][s + 1];
                const uint32_t bl0 = wl2[p][s], bl1 = wl2[p][s + 1];
#pragma unroll
                for (int mt = 0; mt < 2; mt++) {
                    mma16816(acc[mt][ntt], ah[mt], bh0, bh1);
                    mma16816(acc[mt][ntt], ah[mt], bl0, bl1);
                    mma16816(acc[mt][ntt], al[mt], bh0, bh1);
                }
            }
        }

        // ---- Epilogue ----
#pragma unroll
        for (int mt = 0; mt < 2; mt++) {
            int r0 = m0 + mrow + mt * 16 + grp;
#pragma unroll
            for (int ntt = 0; ntt < 4; ntt++) {
                int c = n0 + ncol + ntt * 8 + thr4 * 2;
                float bx = 0.f, by = 0.f;
                if (bias) { bx = bias[c]; by = bias[c + 1]; }
                float2 v0 = make_float2(acc[mt][ntt][0] + bx, acc[mt][ntt][1] + by);
                float2 v1 = make_float2(acc[mt][ntt][2] + bx, acc[mt][ntt][3] + by);
                *reinterpret_cast<float2*>(C + (size_t)r0 * ldc + c) = v0;
                *reinterpret_cast<float2*>(C + (size_t)(r0 + 8) * ldc + c) = v1;
            }
        }
        __syncthreads();
    }
}

// ============================================================================
// Windowed attention, warp-autonomous (R14, measured-good).
// ============================================================================
__global__ __launch_bounds__(224) void attn_kernel()
{
    const int idx = blockIdx.x;
    const int h = idx & 3;
    const int g = (idx >> 2) & 63;
    const int b = idx >> 8;
    const int gy = g >> 3, gx = g & 7;

    __shared__ __align__(16) float vs[49][36];
    __shared__ __align__(16) float S[49 * 52];
    __shared__ float qs[49][33];
    __shared__ float ks[49][33];

    const int tid = threadIdx.x;

    for (int l = tid; l < 49 * 32; l += 224) {
        int i = l >> 5, c = l & 31;
        int n = (gy * 7 + i / 7) * 56 + gx * 7 + (i % 7);
        size_t base = ((size_t)b * N_ + n) * 384 + h * 32 + c;
        qs[i][c] = g_qkv[base];
        ks[i][c] = g_qkv[base + 128];
        vs[i][c] = g_qkv[base + 256];
    }
    __syncthreads();

    const float scale = 0.17677669529663687f;   // 32^-0.5
    const int warp = tid >> 5;
    const int lane = tid & 31;
    const int r0 = warp * 7;
    const bool v2 = (lane + 32) < 49;

    float s1[7], s2[7];
#pragma unroll
    for (int rr = 0; rr < 7; rr++) { s1[rr] = 0.f; s2[rr] = 0.f; }
#pragma unroll
    for (int c = 0; c < 32; c++) {
        float k1 = ks[lane][c];
        float k2 = v2 ? ks[lane + 32][c] : 0.f;
#pragma unroll
        for (int rr = 0; rr < 7; rr++) {
            float q = qs[r0 + rr][c];
            s1[rr] += q * k1;
            s2[rr] += q * k2;
        }
    }

#pragma unroll
    for (int rr = 0; rr < 7; rr++) {
        float a = s1[rr] * scale;
        float bb = v2 ? s2[rr] * scale : -1e30f;
        float m = fmaxf(a, bb);
#pragma unroll
        for (int o = 16; o >= 1; o >>= 1)
            m = fmaxf(m, __shfl_xor_sync(0xffffffffu, m, o));
        float e1 = __expf(a - m);
        float e2 = v2 ? __expf(bb - m) : 0.f;
        float sum = e1 + e2;
#pragma unroll
        for (int o = 16; o >= 1; o >>= 1)
            sum += __shfl_xor_sync(0xffffffffu, sum, o);
        float inv = __fdividef(1.f, sum);
        S[(r0 + rr) * 52 + lane] = e1 * inv;
        if (v2) S[(r0 + rr) * 52 + lane + 32] = e2 * inv;
    }
    __syncwarp();

    if (lane < 28) {
        const int rr = lane >> 2;
        const int d0 = (lane & 3) * 8;
        const int r = r0 + rr;
        float acc[8];
#pragma unroll
        for (int d = 0; d < 8; d++) acc[d] = 0.f;
        const float* Sr = S + r * 52;
        for (int j = 0; j < 49; j++) {
            float p = Sr[j];
            float4 va = *reinterpret_cast<const float4*>(&vs[j][d0]);
            float4 vb = *reinterpret_cast<const float4*>(&vs[j][d0 + 4]);
            acc[0] += p * va.x; acc[1] += p * va.y;
            acc[2] += p * va.z; acc[3] += p * va.w;
            acc[4] += p * vb.x; acc[5] += p * vb.y;
            acc[6] += p * vb.z; acc[7] += p * vb.w;
        }
        int n = (gy * 7 + r / 7) * 56 + gx * 7 + (r % 7);
        float* dst = &g_attn[((size_t)b * N_ + n) * 128 + h * 32 + d0];
        *reinterpret_cast<float4*>(dst) = make_float4(acc[0], acc[1], acc[2], acc[3]);
        *reinterpret_cast<float4*>(dst + 4) = make_float4(acc[4], acc[5], acc[6], acc[7]);
    }
}

// ============================================================================
// Tiled depthwise 3x3 conv on V + bias, float4, 3 CTAs/SM (R14, measured-good).
// ============================================================================
#define CONV_SMEM (10 * 58 * 32 * 4)   // 74240 B

__global__ __launch_bounds__(256, 3) void conv_tiled(
    const float* __restrict__ w_lim, const float* __restrict__ b_lim)
{
    extern __shared__ float vsm[];     // [10 rows][58 x][32 ch]
    const int yt = blockIdx.x;
    const int c0 = blockIdx.y * 32;
    const int b  = blockIdx.z;
    const int y0 = yt * 8;
    const int tid = threadIdx.x;

    for (int l = tid; l < 640; l += 256) {
        int r = l / 64;
        int side = (l >> 5) & 1;
        int c = l & 31;
        vsm[(r * 58 + (side ? 57 : 0)) * 32 + c] = 0.f;
    }
    for (int l = tid; l < 10 * 56 * 32; l += 256) {
        int c = l & 31;
        int x = (l >> 5) % 56;
        int r = (l >> 5) / 56;
        int Y = y0 + r - 1;
        float v = 0.f;
        if ((unsigned)Y < 56u)
            v = g_qkv[((size_t)b * N_ + Y * 56 + x) * 384 + 256 + c0 + c];
        vsm[(r * 58 + x + 1) * 32 + c] = v;
    }

    const int c4 = tid & 7;
    const int xq = tid >> 3;
    const int ch = c4 * 4;

    float4 w4[9];
#pragma unroll
    for (int t = 0; t < 9; t++) {
        w4[t].x = w_lim[(c0 + ch + 0) * 9 + t];
        w4[t].y = w_lim[(c0 + ch + 1) * 9 + t];
        w4[t].z = w_lim[(c0 + ch + 2) * 9 + t];
        w4[t].w = w_lim[(c0 + ch + 3) * 9 + t];
    }
    const float4 bias4 = *reinterpret_cast<const float4*>(b_lim + c0 + ch);

    __syncthreads();

    const float4* vsm4 = reinterpret_cast<const float4*>(vsm);

#pragma unroll
    for (int p = 0; p < 2; p++) {
        const int x = xq + 32 * p;
        if (x >= 56) break;
#pragma unroll
        for (int r = 0; r < 8; r++) {
            float4 acc = bias4;
#pragma unroll
            for (int dy = 0; dy < 3; dy++)
#pragma unroll
                for (int dx = 0; dx < 3; dx++) {
                    float4 v = vsm4[((r + dy) * 58 + x + dx) * 8 + c4];
                    float4 w = w4[dy * 3 + dx];
                    acc.x += w.x * v.x;
                    acc.y += w.y * v.y;
                    acc.z += w.z * v.z;
                    acc.w += w.w * v.w;
                }
            float4* ap = reinterpret_cast<float4*>(
                &g_attn[((size_t)b * N_ + (y0 + r) * 56 + x) * 128 + c0 + ch]);
            float4 o = *ap;
            o.x += acc.x; o.y += acc.y; o.z += acc.z; o.w += acc.w;
            *ap = o;
        }
    }
}

// ============================================================================
extern "C" void kernel_launch(void* const* d_in, const int* in_sizes, int n_in,
                              void* d_out, int out_size)
{
    const float* x      = (const float*)d_in[0];
    const float* w_qkv  = (const float*)d_in[1];
    const float* w_lim  = (const float*)d_in[2];
    const float* b_lim  = (const float*)d_in[3];
    const float* w_proj = (const float*)d_in[4];
    const float* b_proj = (const float*)d_in[5];
    float* out = (float*)d_out;

    float *qkv_ptr, *attn_ptr;
    __nv_bfloat16 *wh_ptr, *wl_ptr;
    cudaGetSymbolAddress((void**)&qkv_ptr,  g_qkv);
    cudaGetSymbolAddress((void**)&attn_ptr, g_attn);
    cudaGetSymbolAddress((void**)&wh_ptr,   g_wh);
    cudaGetSymbolAddress((void**)&wl_ptr,   g_wl);

    cudaFuncSetAttribute(hmma_gemm, cudaFuncAttributeMaxDynamicSharedMemorySize, SM_BYTES);
    cudaFuncSetAttribute(conv_tiled, cudaFuncAttributeMaxDynamicSharedMemorySize, CONV_SMEM);

    // 0) split weights into bf16 hi/lo
    prep_weights<<<(512 * 128 + 255) / 256, 256>>>(w_qkv, w_proj);

    // 1) qkv = x @ w_qkv^T  (A split once, 6 x 64-col W tiles, 2 CTAs/SM)
    hmma_gemm<<<M_TOT / 128, 256, SM_BYTES>>>(x, wh_ptr, wl_ptr, qkv_ptr, 384, 6, nullptr);

    // 2) windowed attention (warp-autonomous)
    attn_kernel<<<B_ * 64 * NHEAD, 224>>>();

    // 3) tiled depthwise conv(v) + b_lim into g_attn (float4, 3 CTAs/SM)
    conv_tiled<<<dim3(7, 4, B_), 256, CONV_SMEM>>>(w_lim, b_lim);

    // 4) out = g_attn @ w_proj^T + b_proj  (2 x 64-col W tiles)
    hmma_gemm<<<M_TOT / 128, 256, SM_BYTES>>>(attn_ptr, wh_ptr + 384 * 128,
                                              wl_ptr + 384 * 128, out, 128, 2, b_proj);
}